// round 8
// baseline (speedup 1.0000x reference)
#include <cuda_runtime.h>
#include <cuda_fp16.h>
#include <cstdint>

// Problem constants
#define NN 50000
#define EE 800000
#define BB 4
#define CC 64
#define NROWS (BB*NN)
#define SBS 256
#define SNB ((NN + SBS - 1) / SBS)

// ---------------- scratch (device globals) ----------------
__device__ int    g_deg[NN];          // zero at load; re-zeroed by k_fill3 each run
__device__ float  g_norm[NN];
__device__ int    g_rowptr[NN + 1];
__device__ int    g_fill[NN];
__device__ int2   g_edge[EE];         // (src, weight-bits)
__device__ __half g_xh[(size_t)NROWS * CC];
__device__ __half g_y1h[(size_t)NROWS * CC];
__device__ __half g_y2h[(size_t)NROWS * CC];

// ---------------- tf32 / mma helpers ----------------
__device__ __forceinline__ unsigned tf32b(float f) {
    unsigned r; asm("cvt.rna.tf32.f32 %0, %1;" : "=r"(r) : "f"(f)); return r;
}
__device__ __forceinline__ void mma8(float* c,
                                     unsigned a0, unsigned a1, unsigned a2, unsigned a3,
                                     unsigned b0, unsigned b1) {
    asm volatile("mma.sync.aligned.m16n8k8.row.col.f32.tf32.tf32.f32 "
                 "{%0,%1,%2,%3}, {%4,%5,%6,%7}, {%8,%9}, {%0,%1,%2,%3};"
                 : "+f"(c[0]), "+f"(c[1]), "+f"(c[2]), "+f"(c[3])
                 : "r"(a0), "r"(a1), "r"(a2), "r"(a3), "r"(b0), "r"(b1));
}

// ---------------- launch 1: degree + x->fp16 convert ----------------
// 800k threads: each converts 16 floats; first EE threads also do one atomic.
__global__ void k_degree_cvt(const int* __restrict__ dst, const float* __restrict__ x) {
    const int tid = blockIdx.x * blockDim.x + threadIdx.x;

    const size_t i16 = (size_t)tid * 16;
    if (i16 < (size_t)NROWS * CC) {
#pragma unroll
        for (int h = 0; h < 2; h++) {
            const size_t i8 = i16 + h * 8;
            float4 a = *(const float4*)(x + i8);
            float4 b = *(const float4*)(x + i8 + 4);
            __half2 hv[4];
            hv[0] = __floats2half2_rn(a.x, a.y);
            hv[1] = __floats2half2_rn(a.z, a.w);
            hv[2] = __floats2half2_rn(b.x, b.y);
            hv[3] = __floats2half2_rn(b.z, b.w);
            *(uint4*)(g_xh + i8) = *(uint4*)hv;
        }
    }

    if (tid < EE) atomicAdd(&g_deg[dst[tid]], 1);
}

// ---------------- launch 2: scan + emit ----------------
__global__ void k_emit2() {
    __shared__ int sh[SBS];
    const int t = threadIdx.x;
    const int i = blockIdx.x * SBS + t;

    const int lim = blockIdx.x * SBS;      // multiple of 256 -> int4-aligned
    int s = 0;
    for (int j = t * 4; j < lim; j += SBS * 4) {
        int4 v = *(const int4*)(g_deg + j);
        s += v.x + v.y + v.z + v.w;
    }
    sh[t] = s;
    __syncthreads();
    for (int off = SBS / 2; off > 0; off >>= 1) {
        if (t < off) sh[t] += sh[t + off];
        __syncthreads();
    }
    const int boff = sh[0];
    __syncthreads();

    const int d = (i < NN) ? g_deg[i] : 0;
    sh[t] = d;
    __syncthreads();
    for (int off = 1; off < SBS; off <<= 1) {
        int u = (t >= off) ? sh[t - off] : 0;
        __syncthreads();
        sh[t] += u;
        __syncthreads();
    }
    if (i < NN) {
        const int rp = boff + sh[t] - d;
        g_rowptr[i] = rp;
        g_fill[i]   = rp;
        g_norm[i]   = rsqrtf((float)(d < 1 ? 1 : d));
    }
    if (i == 0) g_rowptr[NN] = EE;
}

// ---------------- launch 3: fill edges + re-zero deg ----------------
__global__ void k_fill3(const int* __restrict__ src, const int* __restrict__ dst) {
    const int tid = blockIdx.x * blockDim.x + threadIdx.x;

    if (tid < EE) {
        const int d = dst[tid];
        const int s = src[tid];
        const int p = atomicAdd(&g_fill[d], 1);
        g_edge[p] = make_int2(s, __float_as_int(g_norm[s] * g_norm[d]));
    }

    if (tid < NN / 4) ((int4*)g_deg)[tid] = make_int4(0, 0, 0, 0);
}

// ---------------- launches 4,5: SPMM (fp16 gather, fp32 acc, fp16 out) -------
// 1 warp per NPW consecutive dst nodes (imbalance smoothing).
// Edges staged lane-cooperatively (1 coalesced 8B/lane load per <=32 edges),
// broadcast via shfl -> gather LDGs issue back-to-back (high MLP).
// lane -> (batch = lane>>3, chan-octet = (lane&7)*8); 16B gather per edge.
#define NPW 4
__global__ void k_spmm_h(const __half* __restrict__ in_h,
                         const float* __restrict__ addx,
                         __half* __restrict__ out_h,
                         float alpha, float beta) {
    const int warp = (blockIdx.x * blockDim.x + threadIdx.x) >> 5;
    const int node0 = warp * NPW;
    if (node0 >= NN) return;
    const int lane = threadIdx.x & 31;
    const int b  = lane >> 3;
    const int c8 = (lane & 7) * 8;

    const __half* base = in_h + (size_t)b * NN * CC + c8;
    const int nend = min(node0 + NPW, NN);

#pragma unroll
    for (int n = node0; n < nend; n++) {
        const int s0 = g_rowptr[n];
        const int s1 = g_rowptr[n + 1];

        float acc[8];
#pragma unroll
        for (int j = 0; j < 8; j++) acc[j] = 0.f;

        for (int bs = s0; bs < s1; bs += 32) {
            int2 myev = make_int2(0, 0);
            if (bs + lane < s1) myev = g_edge[bs + lane];
            const int cnt = min(32, s1 - bs);
#pragma unroll 4
            for (int j = 0; j < cnt; j++) {
                const int   sidx = __shfl_sync(0xffffffffu, myev.x, j);
                const float w    = __int_as_float(__shfl_sync(0xffffffffu, myev.y, j));
                uint4 v = *(const uint4*)(base + (size_t)sidx * CC);
                const __half2* hp = (const __half2*)&v;
#pragma unroll
                for (int q = 0; q < 4; q++) {
                    float2 f = __half22float2(hp[q]);
                    acc[2 * q]     += w * f.x;
                    acc[2 * q + 1] += w * f.y;
                }
            }
        }

        const size_t o = ((size_t)b * NN + n) * CC + c8;
        float r[8];
#pragma unroll
        for (int j = 0; j < 8; j++) r[j] = alpha * acc[j];
        if (beta != 0.f) {
            float4 a0 = *(const float4*)(addx + o);
            float4 a1 = *(const float4*)(addx + o + 4);
            r[0] += beta * a0.x; r[1] += beta * a0.y; r[2] += beta * a0.z; r[3] += beta * a0.w;
            r[4] += beta * a1.x; r[5] += beta * a1.y; r[6] += beta * a1.z; r[7] += beta * a1.w;
        }
        __half2 h[4];
        h[0] = __floats2half2_rn(r[0], r[1]);
        h[1] = __floats2half2_rn(r[2], r[3]);
        h[2] = __floats2half2_rn(r[4], r[5]);
        h[3] = __floats2half2_rn(r[6], r[7]);
        *(uint4*)(out_h + o) = *(uint4*)h;
    }
}

// ---------------- launch 6: fused dense via tf32 mma.sync --------------------
// out = relu([x|y1|y2] Wc + bc) Wl + bl
// CTA: 128 rows x 64 cols, 256 threads (8 warps). Warp tile 32x32.
#define TR 128
#define NKT1 24          // phase-1 k-steps (K=192)
#define NKT2 8           // phase-2 k-steps (K=64)
#define BSTRIDE 20       // Bf row stride in floats (conflict-free)
#define HPITCH 68        // Hs row pitch in floats

__global__ void __launch_bounds__(256, 1)
k_fused(const float* __restrict__ x,
        const float* __restrict__ Wc, const float* __restrict__ bc,
        const float* __restrict__ Wl, const float* __restrict__ bl,
        float* __restrict__ out) {
    extern __shared__ float sm[];
    float* Af  = sm;                         // 24576 f (phase1 A frags)
    float* Bf  = sm + NKT1 * 8 * 32 * 4;     // 15360 f (phase1 B frags)
    float* Bl2 = Bf + NKT1 * 32 * BSTRIDE;   //  5120 f (phase2 B frags)
    float* bcs = Bl2 + NKT2 * 32 * BSTRIDE;  // 64
    float* bls = bcs + 64;                   // 64
    float* Hs  = Af;                         // overlay: 128*68 f (phase2 A)

    const int t    = threadIdx.x;
    const int lane = t & 31;
    const int w    = t >> 5;
    const int rowbase = blockIdx.x * TR;
    const int nrows = min(TR, NROWS - rowbase);

    // ---- stage Bf (Wc) into fragment layout ----
    for (int s = t; s < NKT1 * 32; s += 256) {
        const int kt = s >> 5, ln = s & 31;
        const int gg = ln >> 2, tt = ln & 3;
        unsigned v[16];
#pragma unroll
        for (int nt = 0; nt < 8; nt++)
#pragma unroll
            for (int j = 0; j < 2; j++)
                v[nt * 2 + j] = tf32b(Wc[(kt * 8 + tt + 4 * j) * 64 + nt * 8 + gg]);
        uint4* dp = (uint4*)(Bf + s * BSTRIDE);
        dp[0] = make_uint4(v[0],  v[1],  v[2],  v[3]);
        dp[1] = make_uint4(v[4],  v[5],  v[6],  v[7]);
        dp[2] = make_uint4(v[8],  v[9],  v[10], v[11]);
        dp[3] = make_uint4(v[12], v[13], v[14], v[15]);
    }
    // ---- stage Bl2 (Wl) ----
    for (int s = t; s < NKT2 * 32; s += 256) {
        const int kt = s >> 5, ln = s & 31;
        const int gg = ln >> 2, tt = ln & 3;
        unsigned v[16];
#pragma unroll
        for (int nt = 0; nt < 8; nt++)
#pragma unroll
            for (int j = 0; j < 2; j++)
                v[nt * 2 + j] = tf32b(Wl[(kt * 8 + tt + 4 * j) * 64 + nt * 8 + gg]);
        uint4* dp = (uint4*)(Bl2 + s * BSTRIDE);
        dp[0] = make_uint4(v[0],  v[1],  v[2],  v[3]);
        dp[1] = make_uint4(v[4],  v[5],  v[6],  v[7]);
        dp[2] = make_uint4(v[8],  v[9],  v[10], v[11]);
        dp[3] = make_uint4(v[12], v[13], v[14], v[15]);
    }
    if (t < 64) { bcs[t] = bc[t]; bls[t] = bl[t]; }

    // ---- stage Af: U = [x | y1h | y2h] rows [rowbase, rowbase+128) ----
    for (int idx = t; idx < NKT1 * 8 * 32; idx += 256) {
        const int kt  = idx >> 8;
        const int rem = idx & 255;
        const int rt  = rem >> 5;
        const int ln  = rem & 31;
        const int gg = ln >> 2, tt = ln & 3;
        const int r0 = rt * 16 + gg;
        const int c0 = kt * 8 + tt;
        float a0 = 0.f, a1 = 0.f, a2 = 0.f, a3 = 0.f;
        if (kt < 8) {
            const float* p = x + (size_t)rowbase * CC;
            if (r0 < nrows)     { a0 = p[(size_t)r0 * CC + c0];
                                  a2 = p[(size_t)r0 * CC + c0 + 4]; }
            if (r0 + 8 < nrows) { a1 = p[(size_t)(r0 + 8) * CC + c0];
                                  a3 = p[(size_t)(r0 + 8) * CC + c0 + 4]; }
        } else {
            const __half* p = ((kt < 16) ? g_y1h : g_y2h) + (size_t)rowbase * CC;
            const int cc = c0 - ((kt < 16) ? 64 : 128);
            if (r0 < nrows)     { a0 = __half2float(p[(size_t)r0 * CC + cc]);
                                  a2 = __half2float(p[(size_t)r0 * CC + cc + 4]); }
            if (r0 + 8 < nrows) { a1 = __half2float(p[(size_t)(r0 + 8) * CC + cc]);
                                  a3 = __half2float(p[(size_t)(r0 + 8) * CC + cc + 4]); }
        }
        *(uint4*)(Af + idx * 4) = make_uint4(tf32b(a0), tf32b(a1), tf32b(a2), tf32b(a3));
    }
    __syncthreads();

    const int mtile = w >> 1;
    const int nt2   = w & 1;
    const int g = lane >> 2, tid = lane & 3;

    // ---- phase 1: h = U @ Wc ----
    float c1[2][4][4];
#pragma unroll
    for (int m = 0; m < 2; m++)
#pragma unroll
        for (int n = 0; n < 4; n++)
#pragma unroll
            for (int q = 0; q < 4; q++) c1[m][n][q] = 0.f;

#pragma unroll 4
    for (int kt = 0; kt < NKT1; kt++) {
        const uint4 A0 = *(const uint4*)(Af + ((kt * 8 + mtile * 2    ) * 32 + lane) * 4);
        const uint4 A1 = *(const uint4*)(Af + ((kt * 8 + mtile * 2 + 1) * 32 + lane) * 4);
        const float* bp = Bf + (kt * 32 + lane) * BSTRIDE + nt2 * 8;
        const uint4 B0 = *(const uint4*)(bp);
        const uint4 B1 = *(const uint4*)(bp + 4);
        mma8(c1[0][0], A0.x, A0.y, A0.z, A0.w, B0.x, B0.y);
        mma8(c1[0][1], A0.x, A0.y, A0.z, A0.w, B0.z, B0.w);
        mma8(c1[0][2], A0.x, A0.y, A0.z, A0.w, B1.x, B1.y);
        mma8(c1[0][3], A0.x, A0.y, A0.z, A0.w, B1.z, B1.w);
        mma8(c1[1][0], A1.x, A1.y, A1.z, A1.w, B0.x, B0.y);
        mma8(c1[1][1], A1.x, A1.y, A1.z, A1.w, B0.z, B0.w);
        mma8(c1[1][2], A1.x, A1.y, A1.z, A1.w, B1.x, B1.y);
        mma8(c1[1][3], A1.x, A1.y, A1.z, A1.w, B1.z, B1.w);
    }
    __syncthreads();

    // ---- epilogue 1: bias + relu -> tf32 bits into Hs ----
#pragma unroll
    for (int m = 0; m < 2; m++) {
        const int R = mtile * 32 + m * 16 + g;
#pragma unroll
        for (int n = 0; n < 4; n++) {
            const int Cl = nt2 * 32 + n * 8 + 2 * tid;
            const float b0 = bcs[Cl], b1 = bcs[Cl + 1];
            const float v0 = fmaxf(c1[m][n][0] + b0, 0.f);
            const float v1 = fmaxf(c1[m][n][1] + b1, 0.f);
            const float v2 = fmaxf(c1[m][n][2] + b0, 0.f);
            const float v3 = fmaxf(c1[m][n][3] + b1, 0.f);
            *(float2*)(Hs + R * HPITCH + Cl) =
                make_float2(__uint_as_float(tf32b(v0)), __uint_as_float(tf32b(v1)));
            *(float2*)(Hs + (R + 8) * HPITCH + Cl) =
                make_float2(__uint_as_float(tf32b(v2)), __uint_as_float(tf32b(v3)));
        }
    }
    __syncthreads();

    // ---- phase 2: out = h @ Wl ----
    float c2[2][4][4];
#pragma unroll
    for (int m = 0; m < 2; m++)
#pragma unroll
        for (int n = 0; n < 4; n++)
#pragma unroll
            for (int q = 0; q < 4; q++) c2[m][n][q] = 0.f;

#pragma unroll
    for (int kt = 0; kt < NKT2; kt++) {
        unsigned a[2][4];
#pragma unroll
        for (int m = 0; m < 2; m++) {
            const int Rb = mtile * 32 + m * 16;
            a[m][0] = __float_as_uint(Hs[(Rb + g    ) * HPITCH + kt * 8 + tid    ]);
            a[m][1] = __float_as_uint(Hs[(Rb + g + 8) * HPITCH + kt * 8 + tid    ]);
            a[m][2] = __float_as_uint(Hs[(Rb + g    ) * HPITCH + kt * 8 + tid + 4]);
            a[m][3] = __float_as_uint(Hs[(Rb + g + 8) * HPITCH + kt * 8 + tid + 4]);
        }
        const float* bp = Bl2 + (kt * 32 + lane) * BSTRIDE + nt2 * 8;
        const uint4 B0 = *(const uint4*)(bp);
        const uint4 B1 = *(const uint4*)(bp + 4);
#pragma unroll
        for (int m = 0; m < 2; m++) {
            mma8(c2[m][0], a[m][0], a[m][1], a[m][2], a[m][3], B0.x, B0.y);
            mma8(c2[m][1], a[m][0], a[m][1], a[m][2], a[m][3], B0.z, B0.w);
            mma8(c2[m][2], a[m][0], a[m][1], a[m][2], a[m][3], B1.x, B1.y);
            mma8(c2[m][3], a[m][0], a[m][1], a[m][2], a[m][3], B1.z, B1.w);
        }
    }

    // ---- epilogue 2: bias + store ----
#pragma unroll
    for (int m = 0; m < 2; m++) {
        const int Rl = mtile * 32 + m * 16 + g;
#pragma unroll
        for (int n = 0; n < 4; n++) {
            const int Cl = nt2 * 32 + n * 8 + 2 * tid;
            const float b0 = bls[Cl], b1 = bls[Cl + 1];
            if (Rl < nrows)
                *(float2*)(out + (size_t)(rowbase + Rl) * CC + Cl) =
                    make_float2(c2[m][n][0] + b0, c2[m][n][1] + b1);
            if (Rl + 8 < nrows)
                *(float2*)(out + (size_t)(rowbase + Rl + 8) * CC + Cl) =
                    make_float2(c2[m][n][2] + b0, c2[m][n][3] + b1);
        }
    }
}

// ---------------- launch ----------------
extern "C" void kernel_launch(void* const* d_in, const int* in_sizes, int n_in,
                              void* d_out, int out_size) {
    const float* x   = (const float*)d_in[0];
    const int*   src = (const int*)d_in[1];
    const int*   dst = (const int*)d_in[2];
    const float* Wc  = (const float*)d_in[3];
    const float* bc  = (const float*)d_in[4];
    const float* Wl  = (const float*)d_in[5];
    const float* bl  = (const float*)d_in[6];
    float* out = (float*)d_out;

    const int fused_smem = (NKT1 * 8 * 32 * 4 + NKT1 * 32 * BSTRIDE +
                            NKT2 * 32 * BSTRIDE + 128) * 4;
    static bool attr_set = false;
    if (!attr_set) {
        cudaFuncSetAttribute(k_fused, cudaFuncAttributeMaxDynamicSharedMemorySize,
                             fused_smem);
        attr_set = true;
    }

    __half *xh, *y1h, *y2h;
    cudaGetSymbolAddress((void**)&xh,  g_xh);
    cudaGetSymbolAddress((void**)&y1h, g_y1h);
    cudaGetSymbolAddress((void**)&y2h, g_y2h);

    // 1: degrees + x->fp16 (800k threads)
    k_degree_cvt<<<(EE + 255) / 256, 256>>>(dst, x);
    // 2: rowptr + norm
    k_emit2<<<SNB, SBS>>>();
    // 3: edge fill + re-zero deg
    k_fill3<<<(EE + 255) / 256, 256>>>(src, dst);
    // 4: y1h = fp16(-(A xh))
    {
        const int warps = (NN + NPW - 1) / NPW;
        k_spmm_h<<<(warps * 32 + 255) / 256, 256>>>(xh, nullptr, y1h, -1.f, 0.f);
    }
    // 5: y2h = fp16(-2 (A y1h) - x)
    {
        const int warps = (NN + NPW - 1) / NPW;
        k_spmm_h<<<(warps * 32 + 255) / 256, 256>>>(y1h, x, y2h, -2.f, -1.f);
    }
    // 6: fused dense (tf32 tensor cores)
    const int nblk = (NROWS + TR - 1) / TR;
    k_fused<<<nblk, 256, fused_smem>>>(x, Wc, bc, Wl, bl, out);
}

// round 9
// speedup vs baseline: 1.0627x; 1.0627x over previous
#include <cuda_runtime.h>
#include <cuda_fp16.h>
#include <cstdint>

// Problem constants
#define NN 50000
#define EE 800000
#define BB 4
#define CC 64
#define NROWS (BB*NN)
#define SBS 256
#define SNB ((NN + SBS - 1) / SBS)

// ---------------- scratch (device globals) ----------------
__device__ int    g_deg[NN];          // zero at load; re-zeroed by k_fill3 each run
__device__ float  g_norm[NN];
__device__ int    g_rowptr[NN + 1];
__device__ int    g_fill[NN];
__device__ int2   g_edge[EE];         // (src, weight-bits)
__device__ __half g_xh[(size_t)NROWS * CC];
__device__ __half g_y1h[(size_t)NROWS * CC];
__device__ __half g_y2h[(size_t)NROWS * CC];

// ---------------- tf32 / mma helpers ----------------
__device__ __forceinline__ unsigned tf32b(float f) {
    unsigned r; asm("cvt.rna.tf32.f32 %0, %1;" : "=r"(r) : "f"(f)); return r;
}
__device__ __forceinline__ void mma8(float* c,
                                     unsigned a0, unsigned a1, unsigned a2, unsigned a3,
                                     unsigned b0, unsigned b1) {
    asm volatile("mma.sync.aligned.m16n8k8.row.col.f32.tf32.tf32.f32 "
                 "{%0,%1,%2,%3}, {%4,%5,%6,%7}, {%8,%9}, {%0,%1,%2,%3};"
                 : "+f"(c[0]), "+f"(c[1]), "+f"(c[2]), "+f"(c[3])
                 : "r"(a0), "r"(a1), "r"(a2), "r"(a3), "r"(b0), "r"(b1));
}

// ---------------- launch 1: degree ----------------
__global__ void k_degree(const int* __restrict__ dst) {
    int e = blockIdx.x * blockDim.x + threadIdx.x;
    if (e < EE) atomicAdd(&g_deg[dst[e]], 1);
}

// ---------------- launch 2: scan + emit ----------------
__global__ void k_emit2() {
    __shared__ int sh[SBS];
    const int t = threadIdx.x;
    const int i = blockIdx.x * SBS + t;

    const int lim = blockIdx.x * SBS;      // multiple of 256 -> int4-aligned
    int s = 0;
    for (int j = t * 4; j < lim; j += SBS * 4) {
        int4 v = *(const int4*)(g_deg + j);
        s += v.x + v.y + v.z + v.w;
    }
    sh[t] = s;
    __syncthreads();
    for (int off = SBS / 2; off > 0; off >>= 1) {
        if (t < off) sh[t] += sh[t + off];
        __syncthreads();
    }
    const int boff = sh[0];
    __syncthreads();

    const int d = (i < NN) ? g_deg[i] : 0;
    sh[t] = d;
    __syncthreads();
    for (int off = 1; off < SBS; off <<= 1) {
        int u = (t >= off) ? sh[t - off] : 0;
        __syncthreads();
        sh[t] += u;
        __syncthreads();
    }
    if (i < NN) {
        const int rp = boff + sh[t] - d;
        g_rowptr[i] = rp;
        g_fill[i]   = rp;
        g_norm[i]   = rsqrtf((float)(d < 1 ? 1 : d));
    }
    if (i == 0) g_rowptr[NN] = EE;
}

// ---------------- launch 3: fill edges + x->fp16 + re-zero deg ----------------
__global__ void k_fill3(const int* __restrict__ src, const int* __restrict__ dst,
                        const float* __restrict__ x) {
    const int tid = blockIdx.x * blockDim.x + threadIdx.x;

    const size_t i8 = (size_t)tid * 8;
    if (i8 < (size_t)NROWS * CC) {
        float4 a = *(const float4*)(x + i8);
        float4 b = *(const float4*)(x + i8 + 4);
        __half2 h[4];
        h[0] = __floats2half2_rn(a.x, a.y);
        h[1] = __floats2half2_rn(a.z, a.w);
        h[2] = __floats2half2_rn(b.x, b.y);
        h[3] = __floats2half2_rn(b.z, b.w);
        *(uint4*)(g_xh + i8) = *(uint4*)h;
    }

    if (tid < EE) {
        const int d = dst[tid];
        const int s = src[tid];
        const int p = atomicAdd(&g_fill[d], 1);
        g_edge[p] = make_int2(s, __float_as_int(g_norm[s] * g_norm[d]));
    }

    if (tid < NN / 4) ((int4*)g_deg)[tid] = make_int4(0, 0, 0, 0);
}

// ---------------- launches 4,5: SPMM (fp16 gather, fp32 acc, fp16 out) -------
// (R6 version: 1 warp per node, direct broadcast edge loads — known-good)
__global__ void k_spmm_h(const __half* __restrict__ in_h,
                         const float* __restrict__ addx,
                         __half* __restrict__ out_h,
                         float alpha, float beta) {
    const int warp = (blockIdx.x * blockDim.x + threadIdx.x) >> 5;
    if (warp >= NN) return;
    const int node = warp;
    const int lane = threadIdx.x & 31;
    const int b  = lane >> 3;
    const int c8 = (lane & 7) * 8;

    const __half* base = in_h + (size_t)b * NN * CC + c8;

    float acc[8];
#pragma unroll
    for (int j = 0; j < 8; j++) acc[j] = 0.f;

    const int s0 = g_rowptr[node];
    const int s1 = g_rowptr[node + 1];

#pragma unroll 4
    for (int e = s0; e < s1; e++) {
        const int2 ev = g_edge[e];
        const float w = __int_as_float(ev.y);
        uint4 v = *(const uint4*)(base + (size_t)ev.x * CC);
        const __half2* hp = (const __half2*)&v;
#pragma unroll
        for (int j = 0; j < 4; j++) {
            float2 f = __half22float2(hp[j]);
            acc[2 * j]     += w * f.x;
            acc[2 * j + 1] += w * f.y;
        }
    }

    const size_t o = ((size_t)b * NN + node) * CC + c8;
    float r[8];
#pragma unroll
    for (int j = 0; j < 8; j++) r[j] = alpha * acc[j];
    if (beta != 0.f) {
        float4 a0 = *(const float4*)(addx + o);
        float4 a1 = *(const float4*)(addx + o + 4);
        r[0] += beta * a0.x; r[1] += beta * a0.y; r[2] += beta * a0.z; r[3] += beta * a0.w;
        r[4] += beta * a1.x; r[5] += beta * a1.y; r[6] += beta * a1.z; r[7] += beta * a1.w;
    }
    __half2 h[4];
    h[0] = __floats2half2_rn(r[0], r[1]);
    h[1] = __floats2half2_rn(r[2], r[3]);
    h[2] = __floats2half2_rn(r[4], r[5]);
    h[3] = __floats2half2_rn(r[6], r[7]);
    *(uint4*)(out_h + o) = *(uint4*)h;
}

// ---------------- launch 6: fused dense via tf32 mma.sync --------------------
// out = relu([x|y1|y2] Wc + bc) Wl + bl
// CTA now covers 256 rows in TWO 128-row passes sharing one weight staging.
// Per pass: 128 rows x 64 cols, 8 warps, warp tile 32x32.
#define TRH 128          // rows per pass
#define TRB 256          // rows per CTA
#define NKT1 24          // phase-1 k-steps (K=192)
#define NKT2 8           // phase-2 k-steps (K=64)
#define BSTRIDE 20       // Bf row stride in floats (conflict-free)
#define HPITCH 68        // Hs row pitch in floats

__global__ void __launch_bounds__(256, 1)
k_fused(const float* __restrict__ x,
        const float* __restrict__ Wc, const float* __restrict__ bc,
        const float* __restrict__ Wl, const float* __restrict__ bl,
        float* __restrict__ out) {
    extern __shared__ float sm[];
    float* Af  = sm;                         // 24576 f (phase1 A frags, per pass)
    float* Bf  = sm + NKT1 * 8 * 32 * 4;     // 15360 f (phase1 B frags)
    float* Bl2 = Bf + NKT1 * 32 * BSTRIDE;   //  5120 f (phase2 B frags)
    float* bcs = Bl2 + NKT2 * 32 * BSTRIDE;  // 64
    float* bls = bcs + 64;                   // 64
    float* Hs  = Af;                         // overlay: 128*68 f (phase2 A)

    const int t    = threadIdx.x;
    const int lane = t & 31;
    const int w    = t >> 5;

    // ---- stage Bf (Wc) into fragment layout (once per CTA) ----
    for (int s = t; s < NKT1 * 32; s += 256) {
        const int kt = s >> 5, ln = s & 31;
        const int gg = ln >> 2, tt = ln & 3;
        unsigned v[16];
#pragma unroll
        for (int nt = 0; nt < 8; nt++)
#pragma unroll
            for (int j = 0; j < 2; j++)
                v[nt * 2 + j] = tf32b(Wc[(kt * 8 + tt + 4 * j) * 64 + nt * 8 + gg]);
        uint4* dp = (uint4*)(Bf + s * BSTRIDE);
        dp[0] = make_uint4(v[0],  v[1],  v[2],  v[3]);
        dp[1] = make_uint4(v[4],  v[5],  v[6],  v[7]);
        dp[2] = make_uint4(v[8],  v[9],  v[10], v[11]);
        dp[3] = make_uint4(v[12], v[13], v[14], v[15]);
    }
    // ---- stage Bl2 (Wl) ----
    for (int s = t; s < NKT2 * 32; s += 256) {
        const int kt = s >> 5, ln = s & 31;
        const int gg = ln >> 2, tt = ln & 3;
        unsigned v[16];
#pragma unroll
        for (int nt = 0; nt < 8; nt++)
#pragma unroll
            for (int j = 0; j < 2; j++)
                v[nt * 2 + j] = tf32b(Wl[(kt * 8 + tt + 4 * j) * 64 + nt * 8 + gg]);
        uint4* dp = (uint4*)(Bl2 + s * BSTRIDE);
        dp[0] = make_uint4(v[0],  v[1],  v[2],  v[3]);
        dp[1] = make_uint4(v[4],  v[5],  v[6],  v[7]);
        dp[2] = make_uint4(v[8],  v[9],  v[10], v[11]);
        dp[3] = make_uint4(v[12], v[13], v[14], v[15]);
    }
    if (t < 64) { bcs[t] = bc[t]; bls[t] = bl[t]; }

    const int mtile = w >> 1;
    const int nt2   = w & 1;
    const int g = lane >> 2, tid = lane & 3;

    // ======== two 128-row passes sharing the staged weights ========
    for (int half = 0; half < 2; half++) {
        const int rowbase = blockIdx.x * TRB + half * TRH;
        if (rowbase >= NROWS) break;
        const int nrows = min(TRH, NROWS - rowbase);

        // sync: Bf/Bl2 staged (half 0) / previous pass Hs reads done (half 1)
        __syncthreads();

        // ---- stage Af: U = [x | y1h | y2h] rows [rowbase, rowbase+128) ----
        for (int idx = t; idx < NKT1 * 8 * 32; idx += 256) {
            const int kt  = idx >> 8;
            const int rem = idx & 255;
            const int rt  = rem >> 5;
            const int ln  = rem & 31;
            const int gg = ln >> 2, tt = ln & 3;
            const int r0 = rt * 16 + gg;
            const int c0 = kt * 8 + tt;
            float a0 = 0.f, a1 = 0.f, a2 = 0.f, a3 = 0.f;
            if (kt < 8) {
                const float* p = x + (size_t)rowbase * CC;
                if (r0 < nrows)     { a0 = p[(size_t)r0 * CC + c0];
                                      a2 = p[(size_t)r0 * CC + c0 + 4]; }
                if (r0 + 8 < nrows) { a1 = p[(size_t)(r0 + 8) * CC + c0];
                                      a3 = p[(size_t)(r0 + 8) * CC + c0 + 4]; }
            } else {
                const __half* p = ((kt < 16) ? g_y1h : g_y2h) + (size_t)rowbase * CC;
                const int cc = c0 - ((kt < 16) ? 64 : 128);
                if (r0 < nrows)     { a0 = __half2float(p[(size_t)r0 * CC + cc]);
                                      a2 = __half2float(p[(size_t)r0 * CC + cc + 4]); }
                if (r0 + 8 < nrows) { a1 = __half2float(p[(size_t)(r0 + 8) * CC + cc]);
                                      a3 = __half2float(p[(size_t)(r0 + 8) * CC + cc + 4]); }
            }
            *(uint4*)(Af + idx * 4) = make_uint4(tf32b(a0), tf32b(a1), tf32b(a2), tf32b(a3));
        }
        __syncthreads();

        // ---- phase 1: h = U @ Wc ----
        float c1[2][4][4];
#pragma unroll
        for (int m = 0; m < 2; m++)
#pragma unroll
            for (int n = 0; n < 4; n++)
#pragma unroll
                for (int q = 0; q < 4; q++) c1[m][n][q] = 0.f;

#pragma unroll 4
        for (int kt = 0; kt < NKT1; kt++) {
            const uint4 A0 = *(const uint4*)(Af + ((kt * 8 + mtile * 2    ) * 32 + lane) * 4);
            const uint4 A1 = *(const uint4*)(Af + ((kt * 8 + mtile * 2 + 1) * 32 + lane) * 4);
            const float* bp = Bf + (kt * 32 + lane) * BSTRIDE + nt2 * 8;
            const uint4 B0 = *(const uint4*)(bp);
            const uint4 B1 = *(const uint4*)(bp + 4);
            mma8(c1[0][0], A0.x, A0.y, A0.z, A0.w, B0.x, B0.y);
            mma8(c1[0][1], A0.x, A0.y, A0.z, A0.w, B0.z, B0.w);
            mma8(c1[0][2], A0.x, A0.y, A0.z, A0.w, B1.x, B1.y);
            mma8(c1[0][3], A0.x, A0.y, A0.z, A0.w, B1.z, B1.w);
            mma8(c1[1][0], A1.x, A1.y, A1.z, A1.w, B0.x, B0.y);
            mma8(c1[1][1], A1.x, A1.y, A1.z, A1.w, B0.z, B0.w);
            mma8(c1[1][2], A1.x, A1.y, A1.z, A1.w, B1.x, B1.y);
            mma8(c1[1][3], A1.x, A1.y, A1.z, A1.w, B1.z, B1.w);
        }
        __syncthreads();   // all Af reads complete before Hs overlay

        // ---- epilogue 1: bias + relu -> tf32 bits into Hs ----
#pragma unroll
        for (int m = 0; m < 2; m++) {
            const int R = mtile * 32 + m * 16 + g;
#pragma unroll
            for (int n = 0; n < 4; n++) {
                const int Cl = nt2 * 32 + n * 8 + 2 * tid;
                const float b0 = bcs[Cl], b1 = bcs[Cl + 1];
                const float v0 = fmaxf(c1[m][n][0] + b0, 0.f);
                const float v1 = fmaxf(c1[m][n][1] + b1, 0.f);
                const float v2 = fmaxf(c1[m][n][2] + b0, 0.f);
                const float v3 = fmaxf(c1[m][n][3] + b1, 0.f);
                *(float2*)(Hs + R * HPITCH + Cl) =
                    make_float2(__uint_as_float(tf32b(v0)), __uint_as_float(tf32b(v1)));
                *(float2*)(Hs + (R + 8) * HPITCH + Cl) =
                    make_float2(__uint_as_float(tf32b(v2)), __uint_as_float(tf32b(v3)));
            }
        }
        __syncthreads();

        // ---- phase 2: out = h @ Wl ----
        float c2[2][4][4];
#pragma unroll
        for (int m = 0; m < 2; m++)
#pragma unroll
            for (int n = 0; n < 4; n++)
#pragma unroll
                for (int q = 0; q < 4; q++) c2[m][n][q] = 0.f;

#pragma unroll
        for (int kt = 0; kt < NKT2; kt++) {
            unsigned a[2][4];
#pragma unroll
            for (int m = 0; m < 2; m++) {
                const int Rb = mtile * 32 + m * 16;
                a[m][0] = __float_as_uint(Hs[(Rb + g    ) * HPITCH + kt * 8 + tid    ]);
                a[m][1] = __float_as_uint(Hs[(Rb + g + 8) * HPITCH + kt * 8 + tid    ]);
                a[m][2] = __float_as_uint(Hs[(Rb + g    ) * HPITCH + kt * 8 + tid + 4]);
                a[m][3] = __float_as_uint(Hs[(Rb + g + 8) * HPITCH + kt * 8 + tid + 4]);
            }
            const float* bp = Bl2 + (kt * 32 + lane) * BSTRIDE + nt2 * 8;
            const uint4 B0 = *(const uint4*)(bp);
            const uint4 B1 = *(const uint4*)(bp + 4);
#pragma unroll
            for (int m = 0; m < 2; m++) {
                mma8(c2[m][0], a[m][0], a[m][1], a[m][2], a[m][3], B0.x, B0.y);
                mma8(c2[m][1], a[m][0], a[m][1], a[m][2], a[m][3], B0.z, B0.w);
                mma8(c2[m][2], a[m][0], a[m][1], a[m][2], a[m][3], B1.x, B1.y);
                mma8(c2[m][3], a[m][0], a[m][1], a[m][2], a[m][3], B1.z, B1.w);
            }
        }

        // ---- epilogue 2: bias + store ----
#pragma unroll
        for (int m = 0; m < 2; m++) {
            const int Rl = mtile * 32 + m * 16 + g;
#pragma unroll
            for (int n = 0; n < 4; n++) {
                const int Cl = nt2 * 32 + n * 8 + 2 * tid;
                const float b0 = bls[Cl], b1 = bls[Cl + 1];
                if (Rl < nrows)
                    *(float2*)(out + (size_t)(rowbase + Rl) * CC + Cl) =
                        make_float2(c2[m][n][0] + b0, c2[m][n][1] + b1);
                if (Rl + 8 < nrows)
                    *(float2*)(out + (size_t)(rowbase + Rl + 8) * CC + Cl) =
                        make_float2(c2[m][n][2] + b0, c2[m][n][3] + b1);
            }
        }
    }
}

// ---------------- launch ----------------
extern "C" void kernel_launch(void* const* d_in, const int* in_sizes, int n_in,
                              void* d_out, int out_size) {
    const float* x   = (const float*)d_in[0];
    const int*   src = (const int*)d_in[1];
    const int*   dst = (const int*)d_in[2];
    const float* Wc  = (const float*)d_in[3];
    const float* bc  = (const float*)d_in[4];
    const float* Wl  = (const float*)d_in[5];
    const float* bl  = (const float*)d_in[6];
    float* out = (float*)d_out;

    const int fused_smem = (NKT1 * 8 * 32 * 4 + NKT1 * 32 * BSTRIDE +
                            NKT2 * 32 * BSTRIDE + 128) * 4;
    static bool attr_set = false;
    if (!attr_set) {
        cudaFuncSetAttribute(k_fused, cudaFuncAttributeMaxDynamicSharedMemorySize,
                             fused_smem);
        attr_set = true;
    }

    __half *xh, *y1h, *y2h;
    cudaGetSymbolAddress((void**)&xh,  g_xh);
    cudaGetSymbolAddress((void**)&y1h, g_y1h);
    cudaGetSymbolAddress((void**)&y2h, g_y2h);

    // 1: degrees (g_deg zeroed at load / re-zeroed by k_fill3 each run)
    k_degree<<<(EE + 255) / 256, 256>>>(dst);
    // 2: rowptr + norm
    k_emit2<<<SNB, SBS>>>();
    // 3: edge fill + x->fp16 + re-zero deg
    k_fill3<<<(NROWS * CC / 8 + 255) / 256, 256>>>(src, dst, x);
    // 4: y1h = fp16(-(A xh))
    k_spmm_h<<<(NN + 7) / 8, 256>>>(xh, nullptr, y1h, -1.f, 0.f);
    // 5: y2h = fp16(-2 (A y1h) - x)
    k_spmm_h<<<(NN + 7) / 8, 256>>>(y1h, x, y2h, -2.f, -1.f);
    // 6: fused dense (tf32 tensor cores, 256 rows/CTA, two-pass)
    const int nblk = (NROWS + TRB - 1) / TRB;
    k_fused<<<nblk, 256, fused_smem>>>(x, Wc, bc, Wl, bl, out);
}

// round 10
// speedup vs baseline: 1.4618x; 1.3755x over previous
#include <cuda_runtime.h>
#include <cuda_fp16.h>
#include <cstdint>

// Problem constants
#define NN 50000
#define EE 800000
#define BB 4
#define CC 64
#define NROWS (BB*NN)
#define SBS 256
#define SNB ((NN + SBS - 1) / SBS)

// ---------------- scratch (device globals) ----------------
__device__ int    g_deg[NN];          // zero at load; re-zeroed by k_fill3 each run
__device__ float  g_norm[NN];
__device__ int    g_rowptr[NN + 1];
__device__ int    g_fill[NN];
__device__ int2   g_edge[EE];         // (src, weight-bits)
__device__ __half g_xh[(size_t)NROWS * CC];
__device__ __half g_y1h[(size_t)NROWS * CC];
__device__ __half g_y2h[(size_t)NROWS * CC];

// ---------------- fp16 mma helper ----------------
__device__ __forceinline__ unsigned pkh2(float a, float b) {
    __half2 h = __floats2half2_rn(a, b);
    return *(unsigned*)&h;
}
__device__ __forceinline__ void mma16(float* c,
                                      unsigned a0, unsigned a1, unsigned a2, unsigned a3,
                                      unsigned b0, unsigned b1) {
    asm volatile("mma.sync.aligned.m16n8k16.row.col.f32.f16.f16.f32 "
                 "{%0,%1,%2,%3}, {%4,%5,%6,%7}, {%8,%9}, {%0,%1,%2,%3};"
                 : "+f"(c[0]), "+f"(c[1]), "+f"(c[2]), "+f"(c[3])
                 : "r"(a0), "r"(a1), "r"(a2), "r"(a3), "r"(b0), "r"(b1));
}

// ---------------- launch 1: degree ----------------
__global__ void k_degree(const int* __restrict__ dst) {
    int e = blockIdx.x * blockDim.x + threadIdx.x;
    if (e < EE) atomicAdd(&g_deg[dst[e]], 1);
}

// ---------------- launch 2: scan + emit ----------------
__global__ void k_emit2() {
    __shared__ int sh[SBS];
    const int t = threadIdx.x;
    const int i = blockIdx.x * SBS + t;

    const int lim = blockIdx.x * SBS;      // multiple of 256 -> int4-aligned
    int s = 0;
    for (int j = t * 4; j < lim; j += SBS * 4) {
        int4 v = *(const int4*)(g_deg + j);
        s += v.x + v.y + v.z + v.w;
    }
    sh[t] = s;
    __syncthreads();
    for (int off = SBS / 2; off > 0; off >>= 1) {
        if (t < off) sh[t] += sh[t + off];
        __syncthreads();
    }
    const int boff = sh[0];
    __syncthreads();

    const int d = (i < NN) ? g_deg[i] : 0;
    sh[t] = d;
    __syncthreads();
    for (int off = 1; off < SBS; off <<= 1) {
        int u = (t >= off) ? sh[t - off] : 0;
        __syncthreads();
        sh[t] += u;
        __syncthreads();
    }
    if (i < NN) {
        const int rp = boff + sh[t] - d;
        g_rowptr[i] = rp;
        g_fill[i]   = rp;
        g_norm[i]   = rsqrtf((float)(d < 1 ? 1 : d));
    }
    if (i == 0) g_rowptr[NN] = EE;
}

// ---------------- launch 3: fill edges + x->fp16 + re-zero deg ----------------
__global__ void k_fill3(const int* __restrict__ src, const int* __restrict__ dst,
                        const float* __restrict__ x) {
    const int tid = blockIdx.x * blockDim.x + threadIdx.x;

    const size_t i8 = (size_t)tid * 8;
    if (i8 < (size_t)NROWS * CC) {
        float4 a = *(const float4*)(x + i8);
        float4 b = *(const float4*)(x + i8 + 4);
        __half2 h[4];
        h[0] = __floats2half2_rn(a.x, a.y);
        h[1] = __floats2half2_rn(a.z, a.w);
        h[2] = __floats2half2_rn(b.x, b.y);
        h[3] = __floats2half2_rn(b.z, b.w);
        *(uint4*)(g_xh + i8) = *(uint4*)h;
    }

    if (tid < EE) {
        const int d = dst[tid];
        const int s = src[tid];
        const int p = atomicAdd(&g_fill[d], 1);
        g_edge[p] = make_int2(s, __float_as_int(g_norm[s] * g_norm[d]));
    }

    if (tid < NN / 4) ((int4*)g_deg)[tid] = make_int4(0, 0, 0, 0);
}

// ---------------- launches 4,5: SPMM (fp16 gather, fp32 acc, fp16 out) -------
// (known-good R6 version: 1 warp per node, direct broadcast edge loads)
__global__ void k_spmm_h(const __half* __restrict__ in_h,
                         const float* __restrict__ addx,
                         __half* __restrict__ out_h,
                         float alpha, float beta) {
    const int warp = (blockIdx.x * blockDim.x + threadIdx.x) >> 5;
    if (warp >= NN) return;
    const int node = warp;
    const int lane = threadIdx.x & 31;
    const int b  = lane >> 3;
    const int c8 = (lane & 7) * 8;

    const __half* base = in_h + (size_t)b * NN * CC + c8;

    float acc[8];
#pragma unroll
    for (int j = 0; j < 8; j++) acc[j] = 0.f;

    const int s0 = g_rowptr[node];
    const int s1 = g_rowptr[node + 1];

#pragma unroll 4
    for (int e = s0; e < s1; e++) {
        const int2 ev = g_edge[e];
        const float w = __int_as_float(ev.y);
        uint4 v = *(const uint4*)(base + (size_t)ev.x * CC);
        const __half2* hp = (const __half2*)&v;
#pragma unroll
        for (int j = 0; j < 4; j++) {
            float2 f = __half22float2(hp[j]);
            acc[2 * j]     += w * f.x;
            acc[2 * j + 1] += w * f.y;
        }
    }

    const size_t o = ((size_t)b * NN + node) * CC + c8;
    float r[8];
#pragma unroll
    for (int j = 0; j < 8; j++) r[j] = alpha * acc[j];
    if (beta != 0.f) {
        float4 a0 = *(const float4*)(addx + o);
        float4 a1 = *(const float4*)(addx + o + 4);
        r[0] += beta * a0.x; r[1] += beta * a0.y; r[2] += beta * a0.z; r[3] += beta * a0.w;
        r[4] += beta * a1.x; r[5] += beta * a1.y; r[6] += beta * a1.z; r[7] += beta * a1.w;
    }
    __half2 h[4];
    h[0] = __floats2half2_rn(r[0], r[1]);
    h[1] = __floats2half2_rn(r[2], r[3]);
    h[2] = __floats2half2_rn(r[4], r[5]);
    h[3] = __floats2half2_rn(r[6], r[7]);
    *(uint4*)(out_h + o) = *(uint4*)h;
}

// ---------------- launch 6: fused dense via fp16 mma m16n8k16 ----------------
// out = relu([xh|y1h|y2h] Wc + bc) Wl + bl      (fp16 operands, fp32 accumulate)
// CTA: 128 rows x 64 cols, 512 threads (16 warps), warp tile 16x32:
//   mtile = w>>1 (rows 16*mtile..+15), nt2 = w&1 (cols 32*nt2..+31)
// All operands pre-permuted in smem to exact fragment layout.
#define TR 128
#define NKT1 12          // phase-1 k16-steps (K=192)
#define NKT2 4           // phase-2 k16-steps (K=64)
#define BSTRIDE 20       // Bf slot stride in floats (16 data + 4 pad, conflict-free)

__global__ void __launch_bounds__(512, 2)
k_fused(const float* __restrict__ Wc, const float* __restrict__ bc,
        const float* __restrict__ Wl, const float* __restrict__ bl,
        float* __restrict__ out) {
    extern __shared__ float sm[];
    float* Af  = sm;                         // 12*8*32*4 = 12288 f (A frags, f16x2)
    float* Bf  = sm + NKT1 * 8 * 32 * 4;     // 12*32*20  =  7680 f (Wc frags)
    float* Bl2 = Bf + NKT1 * 32 * BSTRIDE;   //  4*32*20  =  2560 f (Wl frags)
    float* bcs = Bl2 + NKT2 * 32 * BSTRIDE;  // 64
    float* bls = bcs + 64;                   // 64
    float* Hs  = Af;                         // overlay: 4*8*32*4 = 4096 f (phase2 A)

    const int t    = threadIdx.x;
    const int lane = t & 31;
    const int w    = t >> 5;
    const int rowbase = blockIdx.x * TR;
    const int nrows = min(TR, NROWS - rowbase);

    // ---- stage Bf: Wc[192][64] -> fp16 B fragments ----
    // slot s=(kt,ln): v[nt*2]   = {Wc[kt16+2tt][n], Wc[kt16+2tt+1][n]}  (n = nt*8+gg)
    //                 v[nt*2+1] = {Wc[kt16+2tt+8][n], Wc[kt16+2tt+9][n]}
    for (int s = t; s < NKT1 * 32; s += 512) {
        const int kt = s >> 5, ln = s & 31;
        const int gg = ln >> 2, tt = ln & 3;
        const int k0 = kt * 16 + 2 * tt;
        unsigned v[16];
#pragma unroll
        for (int nt = 0; nt < 8; nt++) {
            const int n = nt * 8 + gg;
            v[nt * 2]     = pkh2(Wc[(k0)     * 64 + n], Wc[(k0 + 1) * 64 + n]);
            v[nt * 2 + 1] = pkh2(Wc[(k0 + 8) * 64 + n], Wc[(k0 + 9) * 64 + n]);
        }
        uint4* dp = (uint4*)(Bf + s * BSTRIDE);
        dp[0] = make_uint4(v[0],  v[1],  v[2],  v[3]);
        dp[1] = make_uint4(v[4],  v[5],  v[6],  v[7]);
        dp[2] = make_uint4(v[8],  v[9],  v[10], v[11]);
        dp[3] = make_uint4(v[12], v[13], v[14], v[15]);
    }
    // ---- stage Bl2: Wl[64][64] ----
    for (int s = t; s < NKT2 * 32; s += 512) {
        const int kt = s >> 5, ln = s & 31;
        const int gg = ln >> 2, tt = ln & 3;
        const int k0 = kt * 16 + 2 * tt;
        unsigned v[16];
#pragma unroll
        for (int nt = 0; nt < 8; nt++) {
            const int n = nt * 8 + gg;
            v[nt * 2]     = pkh2(Wl[(k0)     * 64 + n], Wl[(k0 + 1) * 64 + n]);
            v[nt * 2 + 1] = pkh2(Wl[(k0 + 8) * 64 + n], Wl[(k0 + 9) * 64 + n]);
        }
        uint4* dp = (uint4*)(Bl2 + s * BSTRIDE);
        dp[0] = make_uint4(v[0],  v[1],  v[2],  v[3]);
        dp[1] = make_uint4(v[4],  v[5],  v[6],  v[7]);
        dp[2] = make_uint4(v[8],  v[9],  v[10], v[11]);
        dp[3] = make_uint4(v[12], v[13], v[14], v[15]);
    }
    if (t < 64) { bcs[t] = bc[t]; bls[t] = bl[t]; }

    // ---- stage Af: U = [xh | y1h | y2h] rows [rowbase, rowbase+128) ----
    // slot idx=(kt,rt,ln): a0=U[r0][c0..c0+1] a1=U[r0+8][..] a2=U[r0][c0+8..] a3=U[r0+8][..]
    for (int idx = t; idx < NKT1 * 8 * 32; idx += 512) {
        const int kt  = idx >> 8;             // /256
        const int rem = idx & 255;
        const int rt  = rem >> 5;
        const int ln  = rem & 31;
        const int gg = ln >> 2, tt = ln & 3;
        const int r0 = rt * 16 + gg;
        const __half* p = (kt < 4) ? g_xh : (kt < 8) ? g_y1h : g_y2h;
        const int c0 = (kt & 3) * 16 + 2 * tt;
        unsigned a0 = 0, a1 = 0, a2 = 0, a3 = 0;
        const __half* pr = p + (size_t)(rowbase) * CC;
        if (r0 < nrows) {
            a0 = *(const unsigned*)(pr + (size_t)r0 * CC + c0);
            a2 = *(const unsigned*)(pr + (size_t)r0 * CC + c0 + 8);
        }
        if (r0 + 8 < nrows) {
            a1 = *(const unsigned*)(pr + (size_t)(r0 + 8) * CC + c0);
            a3 = *(const unsigned*)(pr + (size_t)(r0 + 8) * CC + c0 + 8);
        }
        *(uint4*)(Af + idx * 4) = make_uint4(a0, a1, a2, a3);
    }
    __syncthreads();

    const int mtile = w >> 1;     // 0..7 -> rows 16*mtile
    const int nt2   = w & 1;      // 0..1 -> cols 32*nt2
    const int g = lane >> 2, tid = lane & 3;

    // ---- phase 1: h = U @ Wc ----
    float c1[4][4];
#pragma unroll
    for (int n = 0; n < 4; n++)
#pragma unroll
        for (int q = 0; q < 4; q++) c1[n][q] = 0.f;

#pragma unroll
    for (int kt = 0; kt < NKT1; kt++) {
        const uint4 A = *(const uint4*)(Af + ((kt * 8 + mtile) * 32 + lane) * 4);
        const float* bp = Bf + (kt * 32 + lane) * BSTRIDE + nt2 * 8;
        const uint4 B0 = *(const uint4*)(bp);
        const uint4 B1 = *(const uint4*)(bp + 4);
        mma16(c1[0], A.x, A.y, A.z, A.w, B0.x, B0.y);
        mma16(c1[1], A.x, A.y, A.z, A.w, B0.z, B0.w);
        mma16(c1[2], A.x, A.y, A.z, A.w, B1.x, B1.y);
        mma16(c1[3], A.x, A.y, A.z, A.w, B1.z, B1.w);
    }
    __syncthreads();   // all Af reads complete before Hs overlay

    // ---- epilogue 1: bias + relu -> fp16 A-fragments into Hs ----
    // warp (mtile,nt2): cols C = nt2*32 + n*8 + 2tid (+1); n pairs (2j,2j+1)
    // form A-frag for kt2 = 2*nt2 + j.
#pragma unroll
    for (int j = 0; j < 2; j++) {
        const int kt2 = 2 * nt2 + j;
        float v[4][2];
#pragma unroll
        for (int h = 0; h < 2; h++) {        // n = 2j+h
            const int n = 2 * j + h;
            const int Cl = nt2 * 32 + n * 8 + 2 * tid;
            const float b0 = bcs[Cl], b1 = bcs[Cl + 1];
            v[2 * h][0]     = fmaxf(c1[n][0] + b0, 0.f);   // row g,   col C
            v[2 * h][1]     = fmaxf(c1[n][1] + b1, 0.f);   // row g,   col C+1
            v[2 * h + 1][0] = fmaxf(c1[n][2] + b0, 0.f);   // row g+8, col C
            v[2 * h + 1][1] = fmaxf(c1[n][3] + b1, 0.f);   // row g+8, col C+1
        }
        *(uint4*)(Hs + ((kt2 * 8 + mtile) * 32 + lane) * 4) =
            make_uint4(pkh2(v[0][0], v[0][1]), pkh2(v[1][0], v[1][1]),
                       pkh2(v[2][0], v[2][1]), pkh2(v[3][0], v[3][1]));
    }
    __syncthreads();

    // ---- phase 2: out = h @ Wl ----
    float c2[4][4];
#pragma unroll
    for (int n = 0; n < 4; n++)
#pragma unroll
        for (int q = 0; q < 4; q++) c2[n][q] = 0.f;

#pragma unroll
    for (int kt = 0; kt < NKT2; kt++) {
        const uint4 A = *(const uint4*)(Hs + ((kt * 8 + mtile) * 32 + lane) * 4);
        const float* bp = Bl2 + (kt * 32 + lane) * BSTRIDE + nt2 * 8;
        const uint4 B0 = *(const uint4*)(bp);
        const uint4 B1 = *(const uint4*)(bp + 4);
        mma16(c2[0], A.x, A.y, A.z, A.w, B0.x, B0.y);
        mma16(c2[1], A.x, A.y, A.z, A.w, B0.z, B0.w);
        mma16(c2[2], A.x, A.y, A.z, A.w, B1.x, B1.y);
        mma16(c2[3], A.x, A.y, A.z, A.w, B1.z, B1.w);
    }

    // ---- epilogue 2: bias + store ----
#pragma unroll
    for (int n = 0; n < 4; n++) {
        const int Cl = nt2 * 32 + n * 8 + 2 * tid;
        const float b0 = bls[Cl], b1 = bls[Cl + 1];
        const int Rl = mtile * 16 + g;
        if (Rl < nrows)
            *(float2*)(out + (size_t)(rowbase + Rl) * CC + Cl) =
                make_float2(c2[n][0] + b0, c2[n][1] + b1);
        if (Rl + 8 < nrows)
            *(float2*)(out + (size_t)(rowbase + Rl + 8) * CC + Cl) =
                make_float2(c2[n][2] + b0, c2[n][3] + b1);
    }
}

// ---------------- launch ----------------
extern "C" void kernel_launch(void* const* d_in, const int* in_sizes, int n_in,
                              void* d_out, int out_size) {
    const float* x   = (const float*)d_in[0];
    const int*   src = (const int*)d_in[1];
    const int*   dst = (const int*)d_in[2];
    const float* Wc  = (const float*)d_in[3];
    const float* bc  = (const float*)d_in[4];
    const float* Wl  = (const float*)d_in[5];
    const float* bl  = (const float*)d_in[6];
    float* out = (float*)d_out;

    const int fused_smem = (NKT1 * 8 * 32 * 4 + NKT1 * 32 * BSTRIDE +
                            NKT2 * 32 * BSTRIDE + 128) * 4;   // 90624 B
    static bool attr_set = false;
    if (!attr_set) {
        cudaFuncSetAttribute(k_fused, cudaFuncAttributeMaxDynamicSharedMemorySize,
                             fused_smem);
        attr_set = true;
    }

    __half *xh, *y1h, *y2h;
    cudaGetSymbolAddress((void**)&xh,  g_xh);
    cudaGetSymbolAddress((void**)&y1h, g_y1h);
    cudaGetSymbolAddress((void**)&y2h, g_y2h);

    // 1: degrees (g_deg zeroed at load / re-zeroed by k_fill3 each run)
    k_degree<<<(EE + 255) / 256, 256>>>(dst);
    // 2: rowptr + norm
    k_emit2<<<SNB, SBS>>>();
    // 3: edge fill + x->fp16 + re-zero deg
    k_fill3<<<(NROWS * CC / 8 + 255) / 256, 256>>>(src, dst, x);
    // 4: y1h = fp16(-(A xh))
    k_spmm_h<<<(NN + 7) / 8, 256>>>(xh, nullptr, y1h, -1.f, 0.f);
    // 5: y2h = fp16(-2 (A y1h) - x)
    k_spmm_h<<<(NN + 7) / 8, 256>>>(y1h, x, y2h, -2.f, -1.f);
    // 6: fused dense (fp16 tensor cores, fp32 accumulate)
    const int nblk = (NROWS + TR - 1) / TR;
    k_fused<<<nblk, 512, fused_smem>>>(Wc, bc, Wl, bl, out);
}

// round 11
// speedup vs baseline: 1.5805x; 1.0813x over previous
#include <cuda_runtime.h>
#include <cuda_fp16.h>
#include <cstdint>

// Problem constants
#define NN 50000
#define EE 800000
#define BB 4
#define CC 64
#define NROWS (BB*NN)
#define SBS 256
#define SNB ((NN + SBS - 1) / SBS)

// ---------------- scratch (device globals) ----------------
__device__ int    g_deg[NN];          // zero at load; re-zeroed by k_fill3 each run
__device__ float  g_norm[NN];
__device__ int    g_rowptr[NN + 1];
__device__ int    g_fill[NN];
__device__ int2   g_edge[EE];         // (src, weight-bits)
__device__ __half g_xh[(size_t)NROWS * CC];
__device__ __half g_y1h[(size_t)NROWS * CC];
__device__ __half g_zh[(size_t)NROWS * CC];   // z = A y1 (raw, no scaling)

// ---------------- fp16 mma helper ----------------
__device__ __forceinline__ unsigned pkh2(float a, float b) {
    __half2 h = __floats2half2_rn(a, b);
    return *(unsigned*)&h;
}
__device__ __forceinline__ void mma16(float* c,
                                      unsigned a0, unsigned a1, unsigned a2, unsigned a3,
                                      unsigned b0, unsigned b1) {
    asm volatile("mma.sync.aligned.m16n8k16.row.col.f32.f16.f16.f32 "
                 "{%0,%1,%2,%3}, {%4,%5,%6,%7}, {%8,%9}, {%0,%1,%2,%3};"
                 : "+f"(c[0]), "+f"(c[1]), "+f"(c[2]), "+f"(c[3])
                 : "r"(a0), "r"(a1), "r"(a2), "r"(a3), "r"(b0), "r"(b1));
}

// ---------------- launch 1: degree ----------------
__global__ void k_degree(const int* __restrict__ dst) {
    int e = blockIdx.x * blockDim.x + threadIdx.x;
    if (e < EE) atomicAdd(&g_deg[dst[e]], 1);
}

// ---------------- launch 2: scan + emit ----------------
__global__ void k_emit2() {
    __shared__ int sh[SBS];
    const int t = threadIdx.x;
    const int i = blockIdx.x * SBS + t;

    const int lim = blockIdx.x * SBS;      // multiple of 256 -> int4-aligned
    int s = 0;
    for (int j = t * 4; j < lim; j += SBS * 4) {
        int4 v = *(const int4*)(g_deg + j);
        s += v.x + v.y + v.z + v.w;
    }
    sh[t] = s;
    __syncthreads();
    for (int off = SBS / 2; off > 0; off >>= 1) {
        if (t < off) sh[t] += sh[t + off];
        __syncthreads();
    }
    const int boff = sh[0];
    __syncthreads();

    const int d = (i < NN) ? g_deg[i] : 0;
    sh[t] = d;
    __syncthreads();
    for (int off = 1; off < SBS; off <<= 1) {
        int u = (t >= off) ? sh[t - off] : 0;
        __syncthreads();
        sh[t] += u;
        __syncthreads();
    }
    if (i < NN) {
        const int rp = boff + sh[t] - d;
        g_rowptr[i] = rp;
        g_fill[i]   = rp;
        g_norm[i]   = rsqrtf((float)(d < 1 ? 1 : d));
    }
    if (i == 0) g_rowptr[NN] = EE;
}

// ---------------- launch 3: fill edges + x->fp16 + re-zero deg ----------------
__global__ void k_fill3(const int* __restrict__ src, const int* __restrict__ dst,
                        const float* __restrict__ x) {
    const int tid = blockIdx.x * blockDim.x + threadIdx.x;

    const size_t i8 = (size_t)tid * 8;
    if (i8 < (size_t)NROWS * CC) {
        float4 a = *(const float4*)(x + i8);
        float4 b = *(const float4*)(x + i8 + 4);
        __half2 h[4];
        h[0] = __floats2half2_rn(a.x, a.y);
        h[1] = __floats2half2_rn(a.z, a.w);
        h[2] = __floats2half2_rn(b.x, b.y);
        h[3] = __floats2half2_rn(b.z, b.w);
        *(uint4*)(g_xh + i8) = *(uint4*)h;
    }

    if (tid < EE) {
        const int d = dst[tid];
        const int s = src[tid];
        const int p = atomicAdd(&g_fill[d], 1);
        g_edge[p] = make_int2(s, __float_as_int(g_norm[s] * g_norm[d]));
    }

    if (tid < NN / 4) ((int4*)g_deg)[tid] = make_int4(0, 0, 0, 0);
}

// ---------------- launches 4,5: SPMM  out_h = fp16(alpha * A_hat @ in_h) ----
// 1 warp per dst node; lane -> (batch = lane>>3, chan-octet = (lane&7)*8).
// 2-wide edge pipelining: pairs of independent edge->gather chains per iter.
__global__ void k_spmm_h(const __half* __restrict__ in_h,
                         __half* __restrict__ out_h,
                         float alpha) {
    const int warp = (blockIdx.x * blockDim.x + threadIdx.x) >> 5;
    if (warp >= NN) return;
    const int node = warp;
    const int lane = threadIdx.x & 31;
    const int b  = lane >> 3;
    const int c8 = (lane & 7) * 8;

    const __half* base = in_h + (size_t)b * NN * CC + c8;

    float acc[8];
#pragma unroll
    for (int j = 0; j < 8; j++) acc[j] = 0.f;

    const int s0 = g_rowptr[node];
    const int s1 = g_rowptr[node + 1];

    int e = s0;
#pragma unroll 2
    for (; e + 2 <= s1; e += 2) {
        const int2 ev0 = g_edge[e];
        const int2 ev1 = g_edge[e + 1];
        uint4 v0 = *(const uint4*)(base + (size_t)ev0.x * CC);
        uint4 v1 = *(const uint4*)(base + (size_t)ev1.x * CC);
        const float w0 = __int_as_float(ev0.y);
        const float w1 = __int_as_float(ev1.y);
        const __half2* h0 = (const __half2*)&v0;
        const __half2* h1 = (const __half2*)&v1;
#pragma unroll
        for (int j = 0; j < 4; j++) {
            float2 f0 = __half22float2(h0[j]);
            float2 f1 = __half22float2(h1[j]);
            acc[2 * j]     += w0 * f0.x;
            acc[2 * j + 1] += w0 * f0.y;
            acc[2 * j]     += w1 * f1.x;
            acc[2 * j + 1] += w1 * f1.y;
        }
    }
    if (e < s1) {
        const int2 ev = g_edge[e];
        const float w = __int_as_float(ev.y);
        uint4 v = *(const uint4*)(base + (size_t)ev.x * CC);
        const __half2* hp = (const __half2*)&v;
#pragma unroll
        for (int j = 0; j < 4; j++) {
            float2 f = __half22float2(hp[j]);
            acc[2 * j]     += w * f.x;
            acc[2 * j + 1] += w * f.y;
        }
    }

    const size_t o = ((size_t)b * NN + node) * CC + c8;
    __half2 h[4];
    h[0] = __floats2half2_rn(alpha * acc[0], alpha * acc[1]);
    h[1] = __floats2half2_rn(alpha * acc[2], alpha * acc[3]);
    h[2] = __floats2half2_rn(alpha * acc[4], alpha * acc[5]);
    h[3] = __floats2half2_rn(alpha * acc[6], alpha * acc[7]);
    *(uint4*)(out_h + o) = *(uint4*)h;
}

// ---------------- launch 6: fused dense via fp16 mma m16n8k16 ----------------
// Folded form:  h = relu( xh*(W0-W2) + y1h*W1 + zh*(-2*W2) + bc ),  out = h*Wl + bl
// (z = A y1;  y2 = -2z - x  substituted into the einsum)
// CTA: 128 rows x 64 cols, 512 threads (16 warps), warp tile 16x32.
#define TR 128
#define NKT1 12          // phase-1 k16-steps (K=192)
#define NKT2 4           // phase-2 k16-steps (K=64)
#define BSTRIDE 20       // Bf slot stride in floats (16 data + 4 pad, conflict-free)

__global__ void __launch_bounds__(512, 2)
k_fused(const float* __restrict__ Wc, const float* __restrict__ bc,
        const float* __restrict__ Wl, const float* __restrict__ bl,
        float* __restrict__ out) {
    extern __shared__ float sm[];
    float* Af  = sm;                         // 12*8*32*4 = 12288 f (A frags, f16x2)
    float* Bf  = sm + NKT1 * 8 * 32 * 4;     // 12*32*20  =  7680 f (Wc frags, folded)
    float* Bl2 = Bf + NKT1 * 32 * BSTRIDE;   //  4*32*20  =  2560 f (Wl frags)
    float* bcs = Bl2 + NKT2 * 32 * BSTRIDE;  // 64
    float* bls = bcs + 64;                   // 64
    float* Hs  = Af;                         // overlay: 4*8*32*4 f (phase2 A)

    const int t    = threadIdx.x;
    const int lane = t & 31;
    const int w    = t >> 5;
    const int rowbase = blockIdx.x * TR;
    const int nrows = min(TR, NROWS - rowbase);

    // ---- stage Bf: folded Wc -> fp16 B fragments ----
    // seg0 (k<64):   W0 - W2 ;  seg1: W1 ;  seg2 (k>=128): -2*W2
    for (int s = t; s < NKT1 * 32; s += 512) {
        const int kt = s >> 5, ln = s & 31;
        const int gg = ln >> 2, tt = ln & 3;
        const int k0 = kt * 16 + 2 * tt;
        unsigned v[16];
#pragma unroll
        for (int nt = 0; nt < 8; nt++) {
            const int n = nt * 8 + gg;
            float f[4];
#pragma unroll
            for (int q = 0; q < 4; q++) {
                const int k = k0 + (q & 1) + (q >> 1) * 8;   // k0, k0+1, k0+8, k0+9
                float val = Wc[k * 64 + n];
                if (kt < 4)       val -= Wc[(k + 128) * 64 + n];   // W0 - W2
                else if (kt >= 8) val = -2.f * val;                // -2*W2
                f[q] = val;
            }
            v[nt * 2]     = pkh2(f[0], f[1]);
            v[nt * 2 + 1] = pkh2(f[2], f[3]);
        }
        uint4* dp = (uint4*)(Bf + s * BSTRIDE);
        dp[0] = make_uint4(v[0],  v[1],  v[2],  v[3]);
        dp[1] = make_uint4(v[4],  v[5],  v[6],  v[7]);
        dp[2] = make_uint4(v[8],  v[9],  v[10], v[11]);
        dp[3] = make_uint4(v[12], v[13], v[14], v[15]);
    }
    // ---- stage Bl2: Wl[64][64] ----
    for (int s = t; s < NKT2 * 32; s += 512) {
        const int kt = s >> 5, ln = s & 31;
        const int gg = ln >> 2, tt = ln & 3;
        const int k0 = kt * 16 + 2 * tt;
        unsigned v[16];
#pragma unroll
        for (int nt = 0; nt < 8; nt++) {
            const int n = nt * 8 + gg;
            v[nt * 2]     = pkh2(Wl[(k0)     * 64 + n], Wl[(k0 + 1) * 64 + n]);
            v[nt * 2 + 1] = pkh2(Wl[(k0 + 8) * 64 + n], Wl[(k0 + 9) * 64 + n]);
        }
        uint4* dp = (uint4*)(Bl2 + s * BSTRIDE);
        dp[0] = make_uint4(v[0],  v[1],  v[2],  v[3]);
        dp[1] = make_uint4(v[4],  v[5],  v[6],  v[7]);
        dp[2] = make_uint4(v[8],  v[9],  v[10], v[11]);
        dp[3] = make_uint4(v[12], v[13], v[14], v[15]);
    }
    if (t < 64) { bcs[t] = bc[t]; bls[t] = bl[t]; }

    // ---- stage Af: U = [xh | y1h | zh] rows [rowbase, rowbase+128) ----
    for (int idx = t; idx < NKT1 * 8 * 32; idx += 512) {
        const int kt  = idx >> 8;
        const int rem = idx & 255;
        const int rt  = rem >> 5;
        const int ln  = rem & 31;
        const int gg = ln >> 2, tt = ln & 3;
        const int r0 = rt * 16 + gg;
        const __half* p = (kt < 4) ? g_xh : (kt < 8) ? g_y1h : g_zh;
        const int c0 = (kt & 3) * 16 + 2 * tt;
        unsigned a0 = 0, a1 = 0, a2 = 0, a3 = 0;
        const __half* pr = p + (size_t)(rowbase) * CC;
        if (r0 < nrows) {
            a0 = *(const unsigned*)(pr + (size_t)r0 * CC + c0);
            a2 = *(const unsigned*)(pr + (size_t)r0 * CC + c0 + 8);
        }
        if (r0 + 8 < nrows) {
            a1 = *(const unsigned*)(pr + (size_t)(r0 + 8) * CC + c0);
            a3 = *(const unsigned*)(pr + (size_t)(r0 + 8) * CC + c0 + 8);
        }
        *(uint4*)(Af + idx * 4) = make_uint4(a0, a1, a2, a3);
    }
    __syncthreads();

    const int mtile = w >> 1;     // 0..7 -> rows 16*mtile
    const int nt2   = w & 1;      // 0..1 -> cols 32*nt2
    const int g = lane >> 2, tid = lane & 3;

    // ---- phase 1: h = U @ Wc_folded ----
    float c1[4][4];
#pragma unroll
    for (int n = 0; n < 4; n++)
#pragma unroll
        for (int q = 0; q < 4; q++) c1[n][q] = 0.f;

#pragma unroll
    for (int kt = 0; kt < NKT1; kt++) {
        const uint4 A = *(const uint4*)(Af + ((kt * 8 + mtile) * 32 + lane) * 4);
        const float* bp = Bf + (kt * 32 + lane) * BSTRIDE + nt2 * 8;
        const uint4 B0 = *(const uint4*)(bp);
        const uint4 B1 = *(const uint4*)(bp + 4);
        mma16(c1[0], A.x, A.y, A.z, A.w, B0.x, B0.y);
        mma16(c1[1], A.x, A.y, A.z, A.w, B0.z, B0.w);
        mma16(c1[2], A.x, A.y, A.z, A.w, B1.x, B1.y);
        mma16(c1[3], A.x, A.y, A.z, A.w, B1.z, B1.w);
    }
    __syncthreads();   // all Af reads complete before Hs overlay

    // ---- epilogue 1: bias + relu -> fp16 A-fragments into Hs ----
#pragma unroll
    for (int j = 0; j < 2; j++) {
        const int kt2 = 2 * nt2 + j;
        float v[4][2];
#pragma unroll
        for (int h = 0; h < 2; h++) {
            const int n = 2 * j + h;
            const int Cl = nt2 * 32 + n * 8 + 2 * tid;
            const float b0 = bcs[Cl], b1 = bcs[Cl + 1];
            v[2 * h][0]     = fmaxf(c1[n][0] + b0, 0.f);
            v[2 * h][1]     = fmaxf(c1[n][1] + b1, 0.f);
            v[2 * h + 1][0] = fmaxf(c1[n][2] + b0, 0.f);
            v[2 * h + 1][1] = fmaxf(c1[n][3] + b1, 0.f);
        }
        *(uint4*)(Hs + ((kt2 * 8 + mtile) * 32 + lane) * 4) =
            make_uint4(pkh2(v[0][0], v[0][1]), pkh2(v[1][0], v[1][1]),
                       pkh2(v[2][0], v[2][1]), pkh2(v[3][0], v[3][1]));
    }
    __syncthreads();

    // ---- phase 2: out = h @ Wl ----
    float c2[4][4];
#pragma unroll
    for (int n = 0; n < 4; n++)
#pragma unroll
        for (int q = 0; q < 4; q++) c2[n][q] = 0.f;

#pragma unroll
    for (int kt = 0; kt < NKT2; kt++) {
        const uint4 A = *(const uint4*)(Hs + ((kt * 8 + mtile) * 32 + lane) * 4);
        const float* bp = Bl2 + (kt * 32 + lane) * BSTRIDE + nt2 * 8;
        const uint4 B0 = *(const uint4*)(bp);
        const uint4 B1 = *(const uint4*)(bp + 4);
        mma16(c2[0], A.x, A.y, A.z, A.w, B0.x, B0.y);
        mma16(c2[1], A.x, A.y, A.z, A.w, B0.z, B0.w);
        mma16(c2[2], A.x, A.y, A.z, A.w, B1.x, B1.y);
        mma16(c2[3], A.x, A.y, A.z, A.w, B1.z, B1.w);
    }

    // ---- epilogue 2: bias + store ----
#pragma unroll
    for (int n = 0; n < 4; n++) {
        const int Cl = nt2 * 32 + n * 8 + 2 * tid;
        const float b0 = bls[Cl], b1 = bls[Cl + 1];
        const int Rl = mtile * 16 + g;
        if (Rl < nrows)
            *(float2*)(out + (size_t)(rowbase + Rl) * CC + Cl) =
                make_float2(c2[n][0] + b0, c2[n][1] + b1);
        if (Rl + 8 < nrows)
            *(float2*)(out + (size_t)(rowbase + Rl + 8) * CC + Cl) =
                make_float2(c2[n][2] + b0, c2[n][3] + b1);
    }
}

// ---------------- launch ----------------
extern "C" void kernel_launch(void* const* d_in, const int* in_sizes, int n_in,
                              void* d_out, int out_size) {
    const float* x   = (const float*)d_in[0];
    const int*   src = (const int*)d_in[1];
    const int*   dst = (const int*)d_in[2];
    const float* Wc  = (const float*)d_in[3];
    const float* bc  = (const float*)d_in[4];
    const float* Wl  = (const float*)d_in[5];
    const float* bl  = (const float*)d_in[6];
    float* out = (float*)d_out;

    const int fused_smem = (NKT1 * 8 * 32 * 4 + NKT1 * 32 * BSTRIDE +
                            NKT2 * 32 * BSTRIDE + 128) * 4;   // 90624 B
    static bool attr_set = false;
    if (!attr_set) {
        cudaFuncSetAttribute(k_fused, cudaFuncAttributeMaxDynamicSharedMemorySize,
                             fused_smem);
        attr_set = true;
    }

    __half *xh, *y1h, *zh;
    cudaGetSymbolAddress((void**)&xh,  g_xh);
    cudaGetSymbolAddress((void**)&y1h, g_y1h);
    cudaGetSymbolAddress((void**)&zh,  g_zh);

    // 1: degrees (g_deg zeroed at load / re-zeroed by k_fill3 each run)
    k_degree<<<(EE + 255) / 256, 256>>>(dst);
    // 2: rowptr + norm
    k_emit2<<<SNB, SBS>>>();
    // 3: edge fill + x->fp16 + re-zero deg
    k_fill3<<<(NROWS * CC / 8 + 255) / 256, 256>>>(src, dst, x);
    // 4: y1h = fp16(-(A xh))
    k_spmm_h<<<(NN + 7) / 8, 256>>>(xh, y1h, -1.f);
    // 5: zh = fp16(A y1h)     (y2 = -2z - x folded into GEMM weights)
    k_spmm_h<<<(NN + 7) / 8, 256>>>(y1h, zh, 1.f);
    // 6: fused dense (fp16 tensor cores, folded weights)
    const int nblk = (NROWS + TR - 1) / TR;
    k_fused<<<nblk, 512, fused_smem>>>(Wc, bc, Wl, bl, out);
}

// round 12
// speedup vs baseline: 1.6948x; 1.0723x over previous
#include <cuda_runtime.h>
#include <cuda_fp16.h>
#include <cstdint>

// Problem constants
#define NN 50000
#define EE 800000
#define BB 4
#define CC 64
#define NROWS (BB*NN)
#define SBS 256
#define SNB ((NN + SBS - 1) / SBS)

// ---------------- scratch (device globals) ----------------
__device__ int    g_deg[NN];          // zero at load; re-zeroed by k_fill3 each run
__device__ float  g_norm[NN];
__device__ int    g_rowptr[NN + 1];
__device__ int    g_fill[NN];
__device__ int    g_esrc[EE];         // edge src only (weights hoisted)
__device__ __half g_xt[(size_t)NROWS * CC];    // x~ = norm[s] * x  (gather operand)
__device__ __half g_y1h[(size_t)NROWS * CC];   // y1 (GEMM operand)
__device__ __half g_y1t[(size_t)NROWS * CC];   // norm * y1 (gather operand)
__device__ __half g_zh[(size_t)NROWS * CC];    // z = A y1 (GEMM operand)

// ---------------- fp16 mma helper ----------------
__device__ __forceinline__ unsigned pkh2(float a, float b) {
    __half2 h = __floats2half2_rn(a, b);
    return *(unsigned*)&h;
}
__device__ __forceinline__ void mma16(float* c,
                                      unsigned a0, unsigned a1, unsigned a2, unsigned a3,
                                      unsigned b0, unsigned b1) {
    asm volatile("mma.sync.aligned.m16n8k16.row.col.f32.f16.f16.f32 "
                 "{%0,%1,%2,%3}, {%4,%5,%6,%7}, {%8,%9}, {%0,%1,%2,%3};"
                 : "+f"(c[0]), "+f"(c[1]), "+f"(c[2]), "+f"(c[3])
                 : "r"(a0), "r"(a1), "r"(a2), "r"(a3), "r"(b0), "r"(b1));
}

// ---------------- launch 1: degree ----------------
__global__ void k_degree(const int* __restrict__ dst) {
    int e = blockIdx.x * blockDim.x + threadIdx.x;
    if (e < EE) atomicAdd(&g_deg[dst[e]], 1);
}

// ---------------- launch 2: scan + emit ----------------
__global__ void k_emit2() {
    __shared__ int sh[SBS];
    const int t = threadIdx.x;
    const int i = blockIdx.x * SBS + t;

    const int lim = blockIdx.x * SBS;      // multiple of 256 -> int4-aligned
    int s = 0;
    for (int j = t * 4; j < lim; j += SBS * 4) {
        int4 v = *(const int4*)(g_deg + j);
        s += v.x + v.y + v.z + v.w;
    }
    sh[t] = s;
    __syncthreads();
    for (int off = SBS / 2; off > 0; off >>= 1) {
        if (t < off) sh[t] += sh[t + off];
        __syncthreads();
    }
    const int boff = sh[0];
    __syncthreads();

    const int d = (i < NN) ? g_deg[i] : 0;
    sh[t] = d;
    __syncthreads();
    for (int off = 1; off < SBS; off <<= 1) {
        int u = (t >= off) ? sh[t - off] : 0;
        __syncthreads();
        sh[t] += u;
        __syncthreads();
    }
    if (i < NN) {
        const int rp = boff + sh[t] - d;
        g_rowptr[i] = rp;
        g_fill[i]   = rp;
        g_norm[i]   = rsqrtf((float)(d < 1 ? 1 : d));
    }
    if (i == 0) g_rowptr[NN] = EE;
}

// ---------------- launch 3: fill edges + x->norm-scaled fp16 + re-zero deg ---
__global__ void k_fill3(const int* __restrict__ src, const int* __restrict__ dst,
                        const float* __restrict__ x) {
    const int tid = blockIdx.x * blockDim.x + threadIdx.x;

    // x~ = norm[node] * x, fp16 (8 elems/thread; row = b*NN+node)
    const size_t i8 = (size_t)tid * 8;
    if (i8 < (size_t)NROWS * CC) {
        const int row  = (int)(i8 >> 6);           // /CC
        const int node = row % NN;
        const float nm = g_norm[node];
        float4 a = *(const float4*)(x + i8);
        float4 b = *(const float4*)(x + i8 + 4);
        __half2 h[4];
        h[0] = __floats2half2_rn(nm * a.x, nm * a.y);
        h[1] = __floats2half2_rn(nm * a.z, nm * a.w);
        h[2] = __floats2half2_rn(nm * b.x, nm * b.y);
        h[3] = __floats2half2_rn(nm * b.z, nm * b.w);
        *(uint4*)(g_xt + i8) = *(uint4*)h;
    }

    if (tid < EE) {
        const int d = dst[tid];
        const int p = atomicAdd(&g_fill[d], 1);
        g_esrc[p] = src[tid];
    }

    if (tid < NN / 4) ((int4*)g_deg)[tid] = make_int4(0, 0, 0, 0);
}

// ---------------- launches 4,5: SPMM (weight-hoisted, fp16 HADD2 acc) --------
// in_t is pre-scaled by norm[src]; inner loop is a bare sum (4 HADD2/edge).
// Two alternating half2 accumulator sets (<=~8 fp16 adds each), fp32 combine.
// out_h = fp16(alpha * norm[d] * S);  out_t (optional) = fp16(norm[d] * out_h_val)
__global__ void k_spmm_h(const __half* __restrict__ in_t,
                         __half* __restrict__ out_h,
                         __half* __restrict__ out_t,
                         float alpha) {
    const int warp = (blockIdx.x * blockDim.x + threadIdx.x) >> 5;
    if (warp >= NN) return;
    const int node = warp;
    const int lane = threadIdx.x & 31;
    const int b  = lane >> 3;
    const int c8 = (lane & 7) * 8;

    const __half* base = in_t + (size_t)b * NN * CC + c8;

    __half2 z2 = __float2half2_rn(0.f);
    __half2 acc0[4] = {z2, z2, z2, z2};
    __half2 acc1[4] = {z2, z2, z2, z2};

    const int s0 = g_rowptr[node];
    const int s1 = g_rowptr[node + 1];

    int e = s0;
#pragma unroll 2
    for (; e + 2 <= s1; e += 2) {
        const int sA = g_esrc[e];
        const int sB = g_esrc[e + 1];
        uint4 vA = *(const uint4*)(base + (size_t)sA * CC);
        uint4 vB = *(const uint4*)(base + (size_t)sB * CC);
        const __half2* hA = (const __half2*)&vA;
        const __half2* hB = (const __half2*)&vB;
#pragma unroll
        for (int j = 0; j < 4; j++) {
            acc0[j] = __hadd2(acc0[j], hA[j]);
            acc1[j] = __hadd2(acc1[j], hB[j]);
        }
    }
    if (e < s1) {
        uint4 v = *(const uint4*)(base + (size_t)g_esrc[e] * CC);
        const __half2* hp = (const __half2*)&v;
#pragma unroll
        for (int j = 0; j < 4; j++) acc0[j] = __hadd2(acc0[j], hp[j]);
    }

    const float nrm = g_norm[node];
    const float sc  = alpha * nrm;

    float r[8];
#pragma unroll
    for (int j = 0; j < 4; j++) {
        float2 f0 = __half22float2(acc0[j]);
        float2 f1 = __half22float2(acc1[j]);
        r[2 * j]     = sc * (f0.x + f1.x);
        r[2 * j + 1] = sc * (f0.y + f1.y);
    }

    const size_t o = ((size_t)b * NN + node) * CC + c8;
    __half2 h[4];
    h[0] = __floats2half2_rn(r[0], r[1]);
    h[1] = __floats2half2_rn(r[2], r[3]);
    h[2] = __floats2half2_rn(r[4], r[5]);
    h[3] = __floats2half2_rn(r[6], r[7]);
    *(uint4*)(out_h + o) = *(uint4*)h;

    if (out_t != nullptr) {
        __half2 ht[4];
        ht[0] = __floats2half2_rn(nrm * r[0], nrm * r[1]);
        ht[1] = __floats2half2_rn(nrm * r[2], nrm * r[3]);
        ht[2] = __floats2half2_rn(nrm * r[4], nrm * r[5]);
        ht[3] = __floats2half2_rn(nrm * r[6], nrm * r[7]);
        *(uint4*)(out_t + o) = *(uint4*)ht;
    }
}

// ---------------- launch 6: fused dense via fp16 mma m16n8k16 ----------------
// Folded form:  h = relu( x*(W0-W2) + y1*W1 + z*(-2*W2) + bc ),  out = h*Wl + bl
// CTA: 128 rows x 64 cols, 512 threads (16 warps), warp tile 16x32.
// x staged from fp32 (no plain fp16 copy of x exists anymore).
#define TR 128
#define NKT1 12          // phase-1 k16-steps (K=192)
#define NKT2 4           // phase-2 k16-steps (K=64)
#define BSTRIDE 20       // Bf slot stride in floats (16 data + 4 pad, conflict-free)

__global__ void __launch_bounds__(512, 2)
k_fused(const float* __restrict__ x,
        const float* __restrict__ Wc, const float* __restrict__ bc,
        const float* __restrict__ Wl, const float* __restrict__ bl,
        float* __restrict__ out) {
    extern __shared__ float sm[];
    float* Af  = sm;                         // 12*8*32*4 = 12288 f (A frags, f16x2)
    float* Bf  = sm + NKT1 * 8 * 32 * 4;     // 12*32*20  =  7680 f (Wc frags, folded)
    float* Bl2 = Bf + NKT1 * 32 * BSTRIDE;   //  4*32*20  =  2560 f (Wl frags)
    float* bcs = Bl2 + NKT2 * 32 * BSTRIDE;  // 64
    float* bls = bcs + 64;                   // 64
    float* Hs  = Af;                         // overlay: 4*8*32*4 f (phase2 A)

    const int t    = threadIdx.x;
    const int lane = t & 31;
    const int w    = t >> 5;
    const int rowbase = blockIdx.x * TR;
    const int nrows = min(TR, NROWS - rowbase);

    // ---- stage Bf: folded Wc -> fp16 B fragments ----
    // seg0 (k<64): W0 - W2 ;  seg1: W1 ;  seg2 (k>=128): -2*W2
    for (int s = t; s < NKT1 * 32; s += 512) {
        const int kt = s >> 5, ln = s & 31;
        const int gg = ln >> 2, tt = ln & 3;
        const int k0 = kt * 16 + 2 * tt;
        unsigned v[16];
#pragma unroll
        for (int nt = 0; nt < 8; nt++) {
            const int n = nt * 8 + gg;
            float f[4];
#pragma unroll
            for (int q = 0; q < 4; q++) {
                const int k = k0 + (q & 1) + (q >> 1) * 8;   // k0, k0+1, k0+8, k0+9
                float val = Wc[k * 64 + n];
                if (kt < 4)       val -= Wc[(k + 128) * 64 + n];   // W0 - W2
                else if (kt >= 8) val = -2.f * val;                // -2*W2
                f[q] = val;
            }
            v[nt * 2]     = pkh2(f[0], f[1]);
            v[nt * 2 + 1] = pkh2(f[2], f[3]);
        }
        uint4* dp = (uint4*)(Bf + s * BSTRIDE);
        dp[0] = make_uint4(v[0],  v[1],  v[2],  v[3]);
        dp[1] = make_uint4(v[4],  v[5],  v[6],  v[7]);
        dp[2] = make_uint4(v[8],  v[9],  v[10], v[11]);
        dp[3] = make_uint4(v[12], v[13], v[14], v[15]);
    }
    // ---- stage Bl2: Wl[64][64] ----
    for (int s = t; s < NKT2 * 32; s += 512) {
        const int kt = s >> 5, ln = s & 31;
        const int gg = ln >> 2, tt = ln & 3;
        const int k0 = kt * 16 + 2 * tt;
        unsigned v[16];
#pragma unroll
        for (int nt = 0; nt < 8; nt++) {
            const int n = nt * 8 + gg;
            v[nt * 2]     = pkh2(Wl[(k0)     * 64 + n], Wl[(k0 + 1) * 64 + n]);
            v[nt * 2 + 1] = pkh2(Wl[(k0 + 8) * 64 + n], Wl[(k0 + 9) * 64 + n]);
        }
        uint4* dp = (uint4*)(Bl2 + s * BSTRIDE);
        dp[0] = make_uint4(v[0],  v[1],  v[2],  v[3]);
        dp[1] = make_uint4(v[4],  v[5],  v[6],  v[7]);
        dp[2] = make_uint4(v[8],  v[9],  v[10], v[11]);
        dp[3] = make_uint4(v[12], v[13], v[14], v[15]);
    }
    if (t < 64) { bcs[t] = bc[t]; bls[t] = bl[t]; }

    // ---- stage Af: U = [x(fp32) | y1h | zh] rows [rowbase, rowbase+128) ----
    for (int idx = t; idx < NKT1 * 8 * 32; idx += 512) {
        const int kt  = idx >> 8;
        const int rem = idx & 255;
        const int rt  = rem >> 5;
        const int ln  = rem & 31;
        const int gg = ln >> 2, tt = ln & 3;
        const int r0 = rt * 16 + gg;
        const int c0 = (kt & 3) * 16 + 2 * tt;
        unsigned a0 = 0, a1 = 0, a2 = 0, a3 = 0;
        if (kt < 4) {
            const float* pr = x + (size_t)rowbase * CC;
            if (r0 < nrows) {
                float2 f0 = *(const float2*)(pr + (size_t)r0 * CC + c0);
                float2 f2 = *(const float2*)(pr + (size_t)r0 * CC + c0 + 8);
                a0 = pkh2(f0.x, f0.y);
                a2 = pkh2(f2.x, f2.y);
            }
            if (r0 + 8 < nrows) {
                float2 f1 = *(const float2*)(pr + (size_t)(r0 + 8) * CC + c0);
                float2 f3 = *(const float2*)(pr + (size_t)(r0 + 8) * CC + c0 + 8);
                a1 = pkh2(f1.x, f1.y);
                a3 = pkh2(f3.x, f3.y);
            }
        } else {
            const __half* p = (kt < 8) ? g_y1h : g_zh;
            const __half* pr = p + (size_t)rowbase * CC;
            if (r0 < nrows) {
                a0 = *(const unsigned*)(pr + (size_t)r0 * CC + c0);
                a2 = *(const unsigned*)(pr + (size_t)r0 * CC + c0 + 8);
            }
            if (r0 + 8 < nrows) {
                a1 = *(const unsigned*)(pr + (size_t)(r0 + 8) * CC + c0);
                a3 = *(const unsigned*)(pr + (size_t)(r0 + 8) * CC + c0 + 8);
            }
        }
        *(uint4*)(Af + idx * 4) = make_uint4(a0, a1, a2, a3);
    }
    __syncthreads();

    const int mtile = w >> 1;     // 0..7 -> rows 16*mtile
    const int nt2   = w & 1;      // 0..1 -> cols 32*nt2
    const int g = lane >> 2, tid = lane & 3;

    // ---- phase 1: h = U @ Wc_folded ----
    float c1[4][4];
#pragma unroll
    for (int n = 0; n < 4; n++)
#pragma unroll
        for (int q = 0; q < 4; q++) c1[n][q] = 0.f;

#pragma unroll
    for (int kt = 0; kt < NKT1; kt++) {
        const uint4 A = *(const uint4*)(Af + ((kt * 8 + mtile) * 32 + lane) * 4);
        const float* bp = Bf + (kt * 32 + lane) * BSTRIDE + nt2 * 8;
        const uint4 B0 = *(const uint4*)(bp);
        const uint4 B1 = *(const uint4*)(bp + 4);
        mma16(c1[0], A.x, A.y, A.z, A.w, B0.x, B0.y);
        mma16(c1[1], A.x, A.y, A.z, A.w, B0.z, B0.w);
        mma16(c1[2], A.x, A.y, A.z, A.w, B1.x, B1.y);
        mma16(c1[3], A.x, A.y, A.z, A.w, B1.z, B1.w);
    }
    __syncthreads();   // all Af reads complete before Hs overlay

    // ---- epilogue 1: bias + relu -> fp16 A-fragments into Hs ----
#pragma unroll
    for (int j = 0; j < 2; j++) {
        const int kt2 = 2 * nt2 + j;
        float v[4][2];
#pragma unroll
        for (int h = 0; h < 2; h++) {
            const int n = 2 * j + h;
            const int Cl = nt2 * 32 + n * 8 + 2 * tid;
            const float b0 = bcs[Cl], b1 = bcs[Cl + 1];
            v[2 * h][0]     = fmaxf(c1[n][0] + b0, 0.f);
            v[2 * h][1]     = fmaxf(c1[n][1] + b1, 0.f);
            v[2 * h + 1][0] = fmaxf(c1[n][2] + b0, 0.f);
            v[2 * h + 1][1] = fmaxf(c1[n][3] + b1, 0.f);
        }
        *(uint4*)(Hs + ((kt2 * 8 + mtile) * 32 + lane) * 4) =
            make_uint4(pkh2(v[0][0], v[0][1]), pkh2(v[1][0], v[1][1]),
                       pkh2(v[2][0], v[2][1]), pkh2(v[3][0], v[3][1]));
    }
    __syncthreads();

    // ---- phase 2: out = h @ Wl ----
    float c2[4][4];
#pragma unroll
    for (int n = 0; n < 4; n++)
#pragma unroll
        for (int q = 0; q < 4; q++) c2[n][q] = 0.f;

#pragma unroll
    for (int kt = 0; kt < NKT2; kt++) {
        const uint4 A = *(const uint4*)(Hs + ((kt * 8 + mtile) * 32 + lane) * 4);
        const float* bp = Bl2 + (kt * 32 + lane) * BSTRIDE + nt2 * 8;
        const uint4 B0 = *(const uint4*)(bp);
        const uint4 B1 = *(const uint4*)(bp + 4);
        mma16(c2[0], A.x, A.y, A.z, A.w, B0.x, B0.y);
        mma16(c2[1], A.x, A.y, A.z, A.w, B0.z, B0.w);
        mma16(c2[2], A.x, A.y, A.z, A.w, B1.x, B1.y);
        mma16(c2[3], A.x, A.y, A.z, A.w, B1.z, B1.w);
    }

    // ---- epilogue 2: bias + store ----
#pragma unroll
    for (int n = 0; n < 4; n++) {
        const int Cl = nt2 * 32 + n * 8 + 2 * tid;
        const float b0 = bls[Cl], b1 = bls[Cl + 1];
        const int Rl = mtile * 16 + g;
        if (Rl < nrows)
            *(float2*)(out + (size_t)(rowbase + Rl) * CC + Cl) =
                make_float2(c2[n][0] + b0, c2[n][1] + b1);
        if (Rl + 8 < nrows)
            *(float2*)(out + (size_t)(rowbase + Rl + 8) * CC + Cl) =
                make_float2(c2[n][2] + b0, c2[n][3] + b1);
    }
}

// ---------------- launch ----------------
extern "C" void kernel_launch(void* const* d_in, const int* in_sizes, int n_in,
                              void* d_out, int out_size) {
    const float* x   = (const float*)d_in[0];
    const int*   src = (const int*)d_in[1];
    const int*   dst = (const int*)d_in[2];
    const float* Wc  = (const float*)d_in[3];
    const float* bc  = (const float*)d_in[4];
    const float* Wl  = (const float*)d_in[5];
    const float* bl  = (const float*)d_in[6];
    float* out = (float*)d_out;

    const int fused_smem = (NKT1 * 8 * 32 * 4 + NKT1 * 32 * BSTRIDE +
                            NKT2 * 32 * BSTRIDE + 128) * 4;   // 90624 B
    static bool attr_set = false;
    if (!attr_set) {
        cudaFuncSetAttribute(k_fused, cudaFuncAttributeMaxDynamicSharedMemorySize,
                             fused_smem);
        attr_set = true;
    }

    __half *xt, *y1h, *y1t, *zh;
    cudaGetSymbolAddress((void**)&xt,  g_xt);
    cudaGetSymbolAddress((void**)&y1h, g_y1h);
    cudaGetSymbolAddress((void**)&y1t, g_y1t);
    cudaGetSymbolAddress((void**)&zh,  g_zh);

    // 1: degrees (g_deg zeroed at load / re-zeroed by k_fill3 each run)
    k_degree<<<(EE + 255) / 256, 256>>>(dst);
    // 2: rowptr + norm
    k_emit2<<<SNB, SBS>>>();
    // 3: edge fill + x -> norm-scaled fp16 + re-zero deg
    k_fill3<<<(NROWS * CC / 8 + 255) / 256, 256>>>(src, dst, x);
    // 4: y1 = -norm[d] * sum(x~[src]) ; also y1t = norm*y1 for the next gather
    k_spmm_h<<<(NN + 7) / 8, 256>>>(xt, y1h, y1t, -1.f);
    // 5: z = norm[d] * sum(y1t[src]) = A y1   (y2 folded into GEMM weights)
    k_spmm_h<<<(NN + 7) / 8, 256>>>(y1t, zh, nullptr, 1.f);
    // 6: fused dense (fp16 tensor cores, folded weights)
    const int nblk = (NROWS + TR - 1) / TR;
    k_fused<<<nblk, 512, fused_smem>>>(x, Wc, bc, Wl, bl, out);
}

// round 13
// speedup vs baseline: 1.6955x; 1.0004x over previous
#include <cuda_runtime.h>
#include <cuda_fp16.h>
#include <cstdint>

// Problem constants
#define NN 50000
#define EE 800000
#define BB 4
#define CC 64
#define NROWS (BB*NN)
#define SBS 256
#define SNB ((NN + SBS - 1) / SBS)

// ---------------- scratch (device globals) ----------------
__device__ int    g_deg[NN];          // zero at load; re-zeroed by k_fill3 each run
__device__ float  g_norm[NN];
__device__ int    g_rowptr[NN + 1];
__device__ int    g_fill[NN];
__device__ int    g_esrc[EE];         // edge src only (weights hoisted)
__device__ __half g_xt[(size_t)NROWS * CC];    // x~ = norm[s] * x  (gather operand)
__device__ __half g_y1h[(size_t)NROWS * CC];   // y1 (GEMM operand)
__device__ __half g_y1t[(size_t)NROWS * CC];   // norm * y1 (gather operand)
__device__ __half g_zh[(size_t)NROWS * CC];    // z = A y1 (GEMM operand)

// ---------------- fp16 mma helper ----------------
__device__ __forceinline__ unsigned pkh2(float a, float b) {
    __half2 h = __floats2half2_rn(a, b);
    return *(unsigned*)&h;
}
__device__ __forceinline__ void mma16(float* c,
                                      unsigned a0, unsigned a1, unsigned a2, unsigned a3,
                                      unsigned b0, unsigned b1) {
    asm volatile("mma.sync.aligned.m16n8k16.row.col.f32.f16.f16.f32 "
                 "{%0,%1,%2,%3}, {%4,%5,%6,%7}, {%8,%9}, {%0,%1,%2,%3};"
                 : "+f"(c[0]), "+f"(c[1]), "+f"(c[2]), "+f"(c[3])
                 : "r"(a0), "r"(a1), "r"(a2), "r"(a3), "r"(b0), "r"(b1));
}

// ---------------- launch 1: degree ----------------
__global__ void k_degree(const int* __restrict__ dst) {
    int e = blockIdx.x * blockDim.x + threadIdx.x;
    if (e < EE) atomicAdd(&g_deg[dst[e]], 1);
}

// ---------------- launch 2: scan + emit ----------------
__global__ void k_emit2() {
    __shared__ int sh[SBS];
    const int t = threadIdx.x;
    const int i = blockIdx.x * SBS + t;

    const int lim = blockIdx.x * SBS;      // multiple of 256 -> int4-aligned
    int s = 0;
    for (int j = t * 4; j < lim; j += SBS * 4) {
        int4 v = *(const int4*)(g_deg + j);
        s += v.x + v.y + v.z + v.w;
    }
    sh[t] = s;
    __syncthreads();
    for (int off = SBS / 2; off > 0; off >>= 1) {
        if (t < off) sh[t] += sh[t + off];
        __syncthreads();
    }
    const int boff = sh[0];
    __syncthreads();

    const int d = (i < NN) ? g_deg[i] : 0;
    sh[t] = d;
    __syncthreads();
    for (int off = 1; off < SBS; off <<= 1) {
        int u = (t >= off) ? sh[t - off] : 0;
        __syncthreads();
        sh[t] += u;
        __syncthreads();
    }
    if (i < NN) {
        const int rp = boff + sh[t] - d;
        g_rowptr[i] = rp;
        g_fill[i]   = rp;
        g_norm[i]   = rsqrtf((float)(d < 1 ? 1 : d));
    }
    if (i == 0) g_rowptr[NN] = EE;
}

// ---------------- launch 3: fill edges + x->norm-scaled fp16 + re-zero deg ---
__global__ void k_fill3(const int* __restrict__ src, const int* __restrict__ dst,
                        const float* __restrict__ x) {
    const int tid = blockIdx.x * blockDim.x + threadIdx.x;

    // x~ = norm[node] * x, fp16 (8 elems/thread; row = b*NN+node)
    const size_t i8 = (size_t)tid * 8;
    if (i8 < (size_t)NROWS * CC) {
        const int row  = (int)(i8 >> 6);           // /CC
        const int node = row % NN;
        const float nm = g_norm[node];
        float4 a = *(const float4*)(x + i8);
        float4 b = *(const float4*)(x + i8 + 4);
        __half2 h[4];
        h[0] = __floats2half2_rn(nm * a.x, nm * a.y);
        h[1] = __floats2half2_rn(nm * a.z, nm * a.w);
        h[2] = __floats2half2_rn(nm * b.x, nm * b.y);
        h[3] = __floats2half2_rn(nm * b.z, nm * b.w);
        *(uint4*)(g_xt + i8) = *(uint4*)h;
    }

    if (tid < EE) {
        const int d = dst[tid];
        const int p = atomicAdd(&g_fill[d], 1);
        g_esrc[p] = src[tid];
    }

    if (tid < NN / 4) ((int4*)g_deg)[tid] = make_int4(0, 0, 0, 0);
}

// ---------------- launches 4,5: SPMM (weight-hoisted, fp16 HADD2 acc) --------
// in_t is pre-scaled by norm[src]; inner loop is a bare sum (4 HADD2/edge).
// 4-wide explicit edge pipelining: 4 independent LDG.128 chains in flight.
// Two alternating half2 accumulator sets (<=~8 fp16 adds each), fp32 combine.
__global__ void k_spmm_h(const __half* __restrict__ in_t,
                         __half* __restrict__ out_h,
                         __half* __restrict__ out_t,
                         float alpha) {
    const int warp = (blockIdx.x * blockDim.x + threadIdx.x) >> 5;
    if (warp >= NN) return;
    const int node = warp;
    const int lane = threadIdx.x & 31;
    const int b  = lane >> 3;
    const int c8 = (lane & 7) * 8;

    const __half* base = in_t + (size_t)b * NN * CC + c8;

    __half2 z2 = __float2half2_rn(0.f);
    __half2 acc0[4] = {z2, z2, z2, z2};
    __half2 acc1[4] = {z2, z2, z2, z2};

    const int s0 = g_rowptr[node];
    const int s1 = g_rowptr[node + 1];

    int e = s0;
    for (; e + 4 <= s1; e += 4) {
        const int sA = g_esrc[e];
        const int sB = g_esrc[e + 1];
        const int sC = g_esrc[e + 2];
        const int sD = g_esrc[e + 3];
        uint4 vA = *(const uint4*)(base + (size_t)sA * CC);
        uint4 vB = *(const uint4*)(base + (size_t)sB * CC);
        uint4 vC = *(const uint4*)(base + (size_t)sC * CC);
        uint4 vD = *(const uint4*)(base + (size_t)sD * CC);
        const __half2* hA = (const __half2*)&vA;
        const __half2* hB = (const __half2*)&vB;
        const __half2* hC = (const __half2*)&vC;
        const __half2* hD = (const __half2*)&vD;
#pragma unroll
        for (int j = 0; j < 4; j++) {
            acc0[j] = __hadd2(acc0[j], hA[j]);
            acc1[j] = __hadd2(acc1[j], hB[j]);
            acc0[j] = __hadd2(acc0[j], hC[j]);
            acc1[j] = __hadd2(acc1[j], hD[j]);
        }
    }
    if (e + 2 <= s1) {
        const int sA = g_esrc[e];
        const int sB = g_esrc[e + 1];
        uint4 vA = *(const uint4*)(base + (size_t)sA * CC);
        uint4 vB = *(const uint4*)(base + (size_t)sB * CC);
        const __half2* hA = (const __half2*)&vA;
        const __half2* hB = (const __half2*)&vB;
#pragma unroll
        for (int j = 0; j < 4; j++) {
            acc0[j] = __hadd2(acc0[j], hA[j]);
            acc1[j] = __hadd2(acc1[j], hB[j]);
        }
        e += 2;
    }
    if (e < s1) {
        uint4 v = *(const uint4*)(base + (size_t)g_esrc[e] * CC);
        const __half2* hp = (const __half2*)&v;
#pragma unroll
        for (int j = 0; j < 4; j++) acc0[j] = __hadd2(acc0[j], hp[j]);
    }

    const float nrm = g_norm[node];
    const float sc  = alpha * nrm;

    float r[8];
#pragma unroll
    for (int j = 0; j < 4; j++) {
        float2 f0 = __half22float2(acc0[j]);
        float2 f1 = __half22float2(acc1[j]);
        r[2 * j]     = sc * (f0.x + f1.x);
        r[2 * j + 1] = sc * (f0.y + f1.y);
    }

    const size_t o = ((size_t)b * NN + node) * CC + c8;
    __half2 h[4];
    h[0] = __floats2half2_rn(r[0], r[1]);
    h[1] = __floats2half2_rn(r[2], r[3]);
    h[2] = __floats2half2_rn(r[4], r[5]);
    h[3] = __floats2half2_rn(r[6], r[7]);
    *(uint4*)(out_h + o) = *(uint4*)h;

    if (out_t != nullptr) {
        __half2 ht[4];
        ht[0] = __floats2half2_rn(nrm * r[0], nrm * r[1]);
        ht[1] = __floats2half2_rn(nrm * r[2], nrm * r[3]);
        ht[2] = __floats2half2_rn(nrm * r[4], nrm * r[5]);
        ht[3] = __floats2half2_rn(nrm * r[6], nrm * r[7]);
        *(uint4*)(out_t + o) = *(uint4*)ht;
    }
}

// ---------------- launch 6: fused dense via fp16 mma m16n8k16 ----------------
// Folded form:  h = relu( x*(W0-W2) + y1*W1 + z*(-2*W2) + bc ),  out = h*Wl + bl
// CTA: 128 rows x 64 cols, 512 threads (16 warps), warp tile 16x32.
#define TR 128
#define NKT1 12          // phase-1 k16-steps (K=192)
#define NKT2 4           // phase-2 k16-steps (K=64)
#define BSTRIDE 20       // Bf slot stride in floats (16 data + 4 pad, conflict-free)

__global__ void __launch_bounds__(512, 2)
k_fused(const float* __restrict__ x,
        const float* __restrict__ Wc, const float* __restrict__ bc,
        const float* __restrict__ Wl, const float* __restrict__ bl,
        float* __restrict__ out) {
    extern __shared__ float sm[];
    float* Af  = sm;                         // 12*8*32*4 = 12288 f (A frags, f16x2)
    float* Bf  = sm + NKT1 * 8 * 32 * 4;     // 12*32*20  =  7680 f (Wc frags, folded)
    float* Bl2 = Bf + NKT1 * 32 * BSTRIDE;   //  4*32*20  =  2560 f (Wl frags)
    float* bcs = Bl2 + NKT2 * 32 * BSTRIDE;  // 64
    float* bls = bcs + 64;                   // 64
    float* Hs  = Af;                         // overlay: 4*8*32*4 f (phase2 A)

    const int t    = threadIdx.x;
    const int lane = t & 31;
    const int w    = t >> 5;
    const int rowbase = blockIdx.x * TR;
    const int nrows = min(TR, NROWS - rowbase);

    // ---- stage Bf: folded Wc -> fp16 B fragments ----
    // seg0 (k<64): W0 - W2 ;  seg1: W1 ;  seg2 (k>=128): -2*W2
    for (int s = t; s < NKT1 * 32; s += 512) {
        const int kt = s >> 5, ln = s & 31;
        const int gg = ln >> 2, tt = ln & 3;
        const int k0 = kt * 16 + 2 * tt;
        unsigned v[16];
#pragma unroll
        for (int nt = 0; nt < 8; nt++) {
            const int n = nt * 8 + gg;
            float f[4];
#pragma unroll
            for (int q = 0; q < 4; q++) {
                const int k = k0 + (q & 1) + (q >> 1) * 8;   // k0, k0+1, k0+8, k0+9
                float val = Wc[k * 64 + n];
                if (kt < 4)       val -= Wc[(k + 128) * 64 + n];   // W0 - W2
                else if (kt >= 8) val = -2.f * val;                // -2*W2
                f[q] = val;
            }
            v[nt * 2]     = pkh2(f[0], f[1]);
            v[nt * 2 + 1] = pkh2(f[2], f[3]);
        }
        uint4* dp = (uint4*)(Bf + s * BSTRIDE);
        dp[0] = make_uint4(v[0],  v[1],  v[2],  v[3]);
        dp[1] = make_uint4(v[4],  v[5],  v[6],  v[7]);
        dp[2] = make_uint4(v[8],  v[9],  v[10], v[11]);
        dp[3] = make_uint4(v[12], v[13], v[14], v[15]);
    }
    // ---- stage Bl2: Wl[64][64] ----
    for (int s = t; s < NKT2 * 32; s += 512) {
        const int kt = s >> 5, ln = s & 31;
        const int gg = ln >> 2, tt = ln & 3;
        const int k0 = kt * 16 + 2 * tt;
        unsigned v[16];
#pragma unroll
        for (int nt = 0; nt < 8; nt++) {
            const int n = nt * 8 + gg;
            v[nt * 2]     = pkh2(Wl[(k0)     * 64 + n], Wl[(k0 + 1) * 64 + n]);
            v[nt * 2 + 1] = pkh2(Wl[(k0 + 8) * 64 + n], Wl[(k0 + 9) * 64 + n]);
        }
        uint4* dp = (uint4*)(Bl2 + s * BSTRIDE);
        dp[0] = make_uint4(v[0],  v[1],  v[2],  v[3]);
        dp[1] = make_uint4(v[4],  v[5],  v[6],  v[7]);
        dp[2] = make_uint4(v[8],  v[9],  v[10], v[11]);
        dp[3] = make_uint4(v[12], v[13], v[14], v[15]);
    }
    if (t < 64) { bcs[t] = bc[t]; bls[t] = bl[t]; }

    // ---- stage Af: U = [x(fp32) | y1h | zh] rows [rowbase, rowbase+128) ----
    for (int idx = t; idx < NKT1 * 8 * 32; idx += 512) {
        const int kt  = idx >> 8;
        const int rem = idx & 255;
        const int rt  = rem >> 5;
        const int ln  = rem & 31;
        const int gg = ln >> 2, tt = ln & 3;
        const int r0 = rt * 16 + gg;
        const int c0 = (kt & 3) * 16 + 2 * tt;
        unsigned a0 = 0, a1 = 0, a2 = 0, a3 = 0;
        if (kt < 4) {
            const float* pr = x + (size_t)rowbase * CC;
            if (r0 < nrows) {
                float2 f0 = *(const float2*)(pr + (size_t)r0 * CC + c0);
                float2 f2 = *(const float2*)(pr + (size_t)r0 * CC + c0 + 8);
                a0 = pkh2(f0.x, f0.y);
                a2 = pkh2(f2.x, f2.y);
            }
            if (r0 + 8 < nrows) {
                float2 f1 = *(const float2*)(pr + (size_t)(r0 + 8) * CC + c0);
                float2 f3 = *(const float2*)(pr + (size_t)(r0 + 8) * CC + c0 + 8);
                a1 = pkh2(f1.x, f1.y);
                a3 = pkh2(f3.x, f3.y);
            }
        } else {
            const __half* p = (kt < 8) ? g_y1h : g_zh;
            const __half* pr = p + (size_t)rowbase * CC;
            if (r0 < nrows) {
                a0 = *(const unsigned*)(pr + (size_t)r0 * CC + c0);
                a2 = *(const unsigned*)(pr + (size_t)r0 * CC + c0 + 8);
            }
            if (r0 + 8 < nrows) {
                a1 = *(const unsigned*)(pr + (size_t)(r0 + 8) * CC + c0);
                a3 = *(const unsigned*)(pr + (size_t)(r0 + 8) * CC + c0 + 8);
            }
        }
        *(uint4*)(Af + idx * 4) = make_uint4(a0, a1, a2, a3);
    }
    __syncthreads();

    const int mtile = w >> 1;     // 0..7 -> rows 16*mtile
    const int nt2   = w & 1;      // 0..1 -> cols 32*nt2
    const int g = lane >> 2, tid = lane & 3;

    // ---- phase 1: h = U @ Wc_folded ----
    float c1[4][4];
#pragma unroll
    for (int n = 0; n < 4; n++)
#pragma unroll
        for (int q = 0; q < 4; q++) c1[n][q] = 0.f;

#pragma unroll
    for (int kt = 0; kt < NKT1; kt++) {
        const uint4 A = *(const uint4*)(Af + ((kt * 8 + mtile) * 32 + lane) * 4);
        const float* bp = Bf + (kt * 32 + lane) * BSTRIDE + nt2 * 8;
        const uint4 B0 = *(const uint4*)(bp);
        const uint4 B1 = *(const uint4*)(bp + 4);
        mma16(c1[0], A.x, A.y, A.z, A.w, B0.x, B0.y);
        mma16(c1[1], A.x, A.y, A.z, A.w, B0.z, B0.w);
        mma16(c1[2], A.x, A.y, A.z, A.w, B1.x, B1.y);
        mma16(c1[3], A.x, A.y, A.z, A.w, B1.z, B1.w);
    }
    __syncthreads();   // all Af reads complete before Hs overlay

    // ---- epilogue 1: bias + relu -> fp16 A-fragments into Hs ----
#pragma unroll
    for (int j = 0; j < 2; j++) {
        const int kt2 = 2 * nt2 + j;
        float v[4][2];
#pragma unroll
        for (int h = 0; h < 2; h++) {
            const int n = 2 * j + h;
            const int Cl = nt2 * 32 + n * 8 + 2 * tid;
            const float b0 = bcs[Cl], b1 = bcs[Cl + 1];
            v[2 * h][0]     = fmaxf(c1[n][0] + b0, 0.f);
            v[2 * h][1]     = fmaxf(c1[n][1] + b1, 0.f);
            v[2 * h + 1][0] = fmaxf(c1[n][2] + b0, 0.f);
            v[2 * h + 1][1] = fmaxf(c1[n][3] + b1, 0.f);
        }
        *(uint4*)(Hs + ((kt2 * 8 + mtile) * 32 + lane) * 4) =
            make_uint4(pkh2(v[0][0], v[0][1]), pkh2(v[1][0], v[1][1]),
                       pkh2(v[2][0], v[2][1]), pkh2(v[3][0], v[3][1]));
    }
    __syncthreads();

    // ---- phase 2: out = h @ Wl ----
    float c2[4][4];
#pragma unroll
    for (int n = 0; n < 4; n++)
#pragma unroll
        for (int q = 0; q < 4; q++) c2[n][q] = 0.f;

#pragma unroll
    for (int kt = 0; kt < NKT2; kt++) {
        const uint4 A = *(const uint4*)(Hs + ((kt * 8 + mtile) * 32 + lane) * 4);
        const float* bp = Bl2 + (kt * 32 + lane) * BSTRIDE + nt2 * 8;
        const uint4 B0 = *(const uint4*)(bp);
        const uint4 B1 = *(const uint4*)(bp + 4);
        mma16(c2[0], A.x, A.y, A.z, A.w, B0.x, B0.y);
        mma16(c2[1], A.x, A.y, A.z, A.w, B0.z, B0.w);
        mma16(c2[2], A.x, A.y, A.z, A.w, B1.x, B1.y);
        mma16(c2[3], A.x, A.y, A.z, A.w, B1.z, B1.w);
    }

    // ---- epilogue 2: bias + store ----
#pragma unroll
    for (int n = 0; n < 4; n++) {
        const int Cl = nt2 * 32 + n * 8 + 2 * tid;
        const float b0 = bls[Cl], b1 = bls[Cl + 1];
        const int Rl = mtile * 16 + g;
        if (Rl < nrows)
            *(float2*)(out + (size_t)(rowbase + Rl) * CC + Cl) =
                make_float2(c2[n][0] + b0, c2[n][1] + b1);
        if (Rl + 8 < nrows)
            *(float2*)(out + (size_t)(rowbase + Rl + 8) * CC + Cl) =
                make_float2(c2[n][2] + b0, c2[n][3] + b1);
    }
}

// ---------------- launch ----------------
extern "C" void kernel_launch(void* const* d_in, const int* in_sizes, int n_in,
                              void* d_out, int out_size) {
    const float* x   = (const float*)d_in[0];
    const int*   src = (const int*)d_in[1];
    const int*   dst = (const int*)d_in[2];
    const float* Wc  = (const float*)d_in[3];
    const float* bc  = (const float*)d_in[4];
    const float* Wl  = (const float*)d_in[5];
    const float* bl  = (const float*)d_in[6];
    float* out = (float*)d_out;

    const int fused_smem = (NKT1 * 8 * 32 * 4 + NKT1 * 32 * BSTRIDE +
                            NKT2 * 32 * BSTRIDE + 128) * 4;   // 90624 B
    static bool attr_set = false;
    if (!attr_set) {
        cudaFuncSetAttribute(k_fused, cudaFuncAttributeMaxDynamicSharedMemorySize,
                             fused_smem);
        attr_set = true;
    }

    __half *xt, *y1h, *y1t, *zh;
    cudaGetSymbolAddress((void**)&xt,  g_xt);
    cudaGetSymbolAddress((void**)&y1h, g_y1h);
    cudaGetSymbolAddress((void**)&y1t, g_y1t);
    cudaGetSymbolAddress((void**)&zh,  g_zh);

    // 1: degrees (g_deg zeroed at load / re-zeroed by k_fill3 each run)
    k_degree<<<(EE + 255) / 256, 256>>>(dst);
    // 2: rowptr + norm
    k_emit2<<<SNB, SBS>>>();
    // 3: edge fill + x -> norm-scaled fp16 + re-zero deg
    k_fill3<<<(NROWS * CC / 8 + 255) / 256, 256>>>(src, dst, x);
    // 4: y1 = -norm[d] * sum(x~[src]) ; also y1t = norm*y1 for the next gather
    k_spmm_h<<<(NN + 7) / 8, 256>>>(xt, y1h, y1t, -1.f);
    // 5: z = norm[d] * sum(y1t[src]) = A y1   (y2 folded into GEMM weights)
    k_spmm_h<<<(NN + 7) / 8, 256>>>(y1t, zh, nullptr, 1.f);
    // 6: fused dense (fp16 tensor cores, folded weights)
    const int nblk = (NROWS + TR - 1) / TR;
    k_fused<<<nblk, 512, fused_smem>>>(x, Wc, bc, Wl, bl, out);
}

// round 14
// speedup vs baseline: 1.7309x; 1.0209x over previous
#include <cuda_runtime.h>
#include <cuda_fp16.h>
#include <cstdint>

// Problem constants
#define NN 50000
#define EE 800000
#define BB 4
#define CC 64
#define NROWS (BB*NN)
#define SBS 256
#define SNB ((NN + SBS - 1) / SBS)

// ---------------- scratch (device globals) ----------------
__device__ int    g_deg[NN];          // zero at load; re-zeroed by k_fill3 each run
__device__ float  g_norm[NN];
__device__ int    g_rowptr[NN + 1];
__device__ int    g_rank[EE];         // edge rank within its dst bucket
__device__ int    g_esrc[EE];         // CSR edge src
__device__ __half g_xh[(size_t)NROWS * CC];    // x (fp16, GEMM operand)
__device__ __half g_xt[(size_t)NROWS * CC];    // x~ = norm[s]*x (gather operand)
__device__ __half g_y1h[(size_t)NROWS * CC];   // y1 (GEMM operand)
__device__ __half g_y1t[(size_t)NROWS * CC];   // norm*y1 (gather operand)
__device__ __half g_zh[(size_t)NROWS * CC];    // z = A y1 (GEMM operand)

// ---------------- fp16 mma helper ----------------
__device__ __forceinline__ unsigned pkh2(float a, float b) {
    __half2 h = __floats2half2_rn(a, b);
    return *(unsigned*)&h;
}
__device__ __forceinline__ void mma16(float* c,
                                      unsigned a0, unsigned a1, unsigned a2, unsigned a3,
                                      unsigned b0, unsigned b1) {
    asm volatile("mma.sync.aligned.m16n8k16.row.col.f32.f16.f16.f32 "
                 "{%0,%1,%2,%3}, {%4,%5,%6,%7}, {%8,%9}, {%0,%1,%2,%3};"
                 : "+f"(c[0]), "+f"(c[1]), "+f"(c[2]), "+f"(c[3])
                 : "r"(a0), "r"(a1), "r"(a2), "r"(a3), "r"(b0), "r"(b1));
}

// ---------------- launch 1: degree + rank ----------------
__global__ void k_degree(const int* __restrict__ dst) {
    int e = blockIdx.x * blockDim.x + threadIdx.x;
    if (e < EE) g_rank[e] = atomicAdd(&g_deg[dst[e]], 1);
}

// ---------------- launch 2: scan + emit ----------------
__global__ void k_emit2() {
    __shared__ int sh[SBS];
    const int t = threadIdx.x;
    const int i = blockIdx.x * SBS + t;

    const int lim = blockIdx.x * SBS;      // multiple of 256 -> int4-aligned
    int s = 0;
    for (int j = t * 4; j < lim; j += SBS * 4) {
        int4 v = *(const int4*)(g_deg + j);
        s += v.x + v.y + v.z + v.w;
    }
    sh[t] = s;
    __syncthreads();
    for (int off = SBS / 2; off > 0; off >>= 1) {
        if (t < off) sh[t] += sh[t + off];
        __syncthreads();
    }
    const int boff = sh[0];
    __syncthreads();

    const int d = (i < NN) ? g_deg[i] : 0;
    sh[t] = d;
    __syncthreads();
    for (int off = 1; off < SBS; off <<= 1) {
        int u = (t >= off) ? sh[t - off] : 0;
        __syncthreads();
        sh[t] += u;
        __syncthreads();
    }
    if (i < NN) {
        g_rowptr[i] = boff + sh[t] - d;    // exclusive prefix
        g_norm[i]   = rsqrtf((float)(d < 1 ? 1 : d));
    }
    if (i == 0) g_rowptr[NN] = EE;
}

// ---------------- launch 3: edge fill (atomic-free) + x->fp16 (xh,xt) -------
__global__ void k_fill3(const int* __restrict__ src, const int* __restrict__ dst,
                        const float* __restrict__ x) {
    const int tid = blockIdx.x * blockDim.x + threadIdx.x;

    // xh = fp16(x), xt = fp16(norm[node]*x)   (8 elems/thread)
    const size_t i8 = (size_t)tid * 8;
    if (i8 < (size_t)NROWS * CC) {
        const int row  = (int)(i8 >> 6);           // /CC
        const int node = row % NN;
        const float nm = g_norm[node];
        float4 a = *(const float4*)(x + i8);
        float4 b = *(const float4*)(x + i8 + 4);
        __half2 h[4], ht[4];
        h[0]  = __floats2half2_rn(a.x, a.y);
        h[1]  = __floats2half2_rn(a.z, a.w);
        h[2]  = __floats2half2_rn(b.x, b.y);
        h[3]  = __floats2half2_rn(b.z, b.w);
        ht[0] = __floats2half2_rn(nm * a.x, nm * a.y);
        ht[1] = __floats2half2_rn(nm * a.z, nm * a.w);
        ht[2] = __floats2half2_rn(nm * b.x, nm * b.y);
        ht[3] = __floats2half2_rn(nm * b.z, nm * b.w);
        *(uint4*)(g_xh + i8) = *(uint4*)h;
        *(uint4*)(g_xt + i8) = *(uint4*)ht;
    }

    if (tid < EE) {
        const int d = dst[tid];
        g_esrc[g_rowptr[d] + g_rank[tid]] = src[tid];
    }

    // re-zero g_deg for the next replay (nothing reads g_deg after k_emit2)
    if (tid < NN / 4) ((int4*)g_deg)[tid] = make_int4(0, 0, 0, 0);
}

// ---------------- launches 4,5: SPMM (weight-hoisted, fp16 HADD2 acc) --------
// AT THE LTS THROUGHPUT CAP (410MB L2 reads / ~32us = ~12.9TB/s) — do not
// restructure; only data-volume reductions would help and precision forbids.
__global__ void k_spmm_h(const __half* __restrict__ in_t,
                         __half* __restrict__ out_h,
                         __half* __restrict__ out_t,
                         float alpha) {
    const int warp = (blockIdx.x * blockDim.x + threadIdx.x) >> 5;
    if (warp >= NN) return;
    const int node = warp;
    const int lane = threadIdx.x & 31;
    const int b  = lane >> 3;
    const int c8 = (lane & 7) * 8;

    const __half* base = in_t + (size_t)b * NN * CC + c8;

    __half2 z2 = __float2half2_rn(0.f);
    __half2 acc0[4] = {z2, z2, z2, z2};
    __half2 acc1[4] = {z2, z2, z2, z2};

    const int s0 = g_rowptr[node];
    const int s1 = g_rowptr[node + 1];

    int e = s0;
    for (; e + 4 <= s1; e += 4) {
        const int sA = g_esrc[e];
        const int sB = g_esrc[e + 1];
        const int sC = g_esrc[e + 2];
        const int sD = g_esrc[e + 3];
        uint4 vA = *(const uint4*)(base + (size_t)sA * CC);
        uint4 vB = *(const uint4*)(base + (size_t)sB * CC);
        uint4 vC = *(const uint4*)(base + (size_t)sC * CC);
        uint4 vD = *(const uint4*)(base + (size_t)sD * CC);
        const __half2* hA = (const __half2*)&vA;
        const __half2* hB = (const __half2*)&vB;
        const __half2* hC = (const __half2*)&vC;
        const __half2* hD = (const __half2*)&vD;
#pragma unroll
        for (int j = 0; j < 4; j++) {
            acc0[j] = __hadd2(acc0[j], hA[j]);
            acc1[j] = __hadd2(acc1[j], hB[j]);
            acc0[j] = __hadd2(acc0[j], hC[j]);
            acc1[j] = __hadd2(acc1[j], hD[j]);
        }
    }
    if (e + 2 <= s1) {
        const int sA = g_esrc[e];
        const int sB = g_esrc[e + 1];
        uint4 vA = *(const uint4*)(base + (size_t)sA * CC);
        uint4 vB = *(const uint4*)(base + (size_t)sB * CC);
        const __half2* hA = (const __half2*)&vA;
        const __half2* hB = (const __half2*)&vB;
#pragma unroll
        for (int j = 0; j < 4; j++) {
            acc0[j] = __hadd2(acc0[j], hA[j]);
            acc1[j] = __hadd2(acc1[j], hB[j]);
        }
        e += 2;
    }
    if (e < s1) {
        uint4 v = *(const uint4*)(base + (size_t)g_esrc[e] * CC);
        const __half2* hp = (const __half2*)&v;
#pragma unroll
        for (int j = 0; j < 4; j++) acc0[j] = __hadd2(acc0[j], hp[j]);
    }

    const float nrm = g_norm[node];
    const float sc  = alpha * nrm;

    float r[8];
#pragma unroll
    for (int j = 0; j < 4; j++) {
        float2 f0 = __half22float2(acc0[j]);
        float2 f1 = __half22float2(acc1[j]);
        r[2 * j]     = sc * (f0.x + f1.x);
        r[2 * j + 1] = sc * (f0.y + f1.y);
    }

    const size_t o = ((size_t)b * NN + node) * CC + c8;
    __half2 h[4];
    h[0] = __floats2half2_rn(r[0], r[1]);
    h[1] = __floats2half2_rn(r[2], r[3]);
    h[2] = __floats2half2_rn(r[4], r[5]);
    h[3] = __floats2half2_rn(r[6], r[7]);
    *(uint4*)(out_h + o) = *(uint4*)h;

    if (out_t != nullptr) {
        __half2 ht[4];
        ht[0] = __floats2half2_rn(nrm * r[0], nrm * r[1]);
        ht[1] = __floats2half2_rn(nrm * r[2], nrm * r[3]);
        ht[2] = __floats2half2_rn(nrm * r[4], nrm * r[5]);
        ht[3] = __floats2half2_rn(nrm * r[6], nrm * r[7]);
        *(uint4*)(out_t + o) = *(uint4*)ht;
    }
}

// ---------------- launch 6: fused dense via fp16 mma m16n8k16 ----------------
// Folded form:  h = relu( x*(W0-W2) + y1*W1 + z*(-2*W2) + bc ),  out = h*Wl + bl
// CTA: 128 rows x 64 cols, 512 threads (16 warps), warp tile 16x32.
// All three A segments staged from fp16 (xh | y1h | zh) — uniform path.
#define TR 128
#define NKT1 12          // phase-1 k16-steps (K=192)
#define NKT2 4           // phase-2 k16-steps (K=64)
#define BSTRIDE 20       // Bf slot stride in floats (16 data + 4 pad, conflict-free)

__global__ void __launch_bounds__(512, 2)
k_fused(const float* __restrict__ Wc, const float* __restrict__ bc,
        const float* __restrict__ Wl, const float* __restrict__ bl,
        float* __restrict__ out) {
    extern __shared__ float sm[];
    float* Af  = sm;                         // 12*8*32*4 = 12288 f (A frags, f16x2)
    float* Bf  = sm + NKT1 * 8 * 32 * 4;     // 12*32*20  =  7680 f (Wc frags, folded)
    float* Bl2 = Bf + NKT1 * 32 * BSTRIDE;   //  4*32*20  =  2560 f (Wl frags)
    float* bcs = Bl2 + NKT2 * 32 * BSTRIDE;  // 64
    float* bls = bcs + 64;                   // 64
    float* Hs  = Af;                         // overlay: 4*8*32*4 f (phase2 A)

    const int t    = threadIdx.x;
    const int lane = t & 31;
    const int w    = t >> 5;
    const int rowbase = blockIdx.x * TR;
    const int nrows = min(TR, NROWS - rowbase);

    // ---- stage Bf: folded Wc -> fp16 B fragments ----
    // seg0 (k<64): W0 - W2 ;  seg1: W1 ;  seg2 (k>=128): -2*W2
    for (int s = t; s < NKT1 * 32; s += 512) {
        const int kt = s >> 5, ln = s & 31;
        const int gg = ln >> 2, tt = ln & 3;
        const int k0 = kt * 16 + 2 * tt;
        unsigned v[16];
#pragma unroll
        for (int nt = 0; nt < 8; nt++) {
            const int n = nt * 8 + gg;
            float f[4];
#pragma unroll
            for (int q = 0; q < 4; q++) {
                const int k = k0 + (q & 1) + (q >> 1) * 8;   // k0, k0+1, k0+8, k0+9
                float val = Wc[k * 64 + n];
                if (kt < 4)       val -= Wc[(k + 128) * 64 + n];   // W0 - W2
                else if (kt >= 8) val = -2.f * val;                // -2*W2
                f[q] = val;
            }
            v[nt * 2]     = pkh2(f[0], f[1]);
            v[nt * 2 + 1] = pkh2(f[2], f[3]);
        }
        uint4* dp = (uint4*)(Bf + s * BSTRIDE);
        dp[0] = make_uint4(v[0],  v[1],  v[2],  v[3]);
        dp[1] = make_uint4(v[4],  v[5],  v[6],  v[7]);
        dp[2] = make_uint4(v[8],  v[9],  v[10], v[11]);
        dp[3] = make_uint4(v[12], v[13], v[14], v[15]);
    }
    // ---- stage Bl2: Wl[64][64] ----
    for (int s = t; s < NKT2 * 32; s += 512) {
        const int kt = s >> 5, ln = s & 31;
        const int gg = ln >> 2, tt = ln & 3;
        const int k0 = kt * 16 + 2 * tt;
        unsigned v[16];
#pragma unroll
        for (int nt = 0; nt < 8; nt++) {
            const int n = nt * 8 + gg;
            v[nt * 2]     = pkh2(Wl[(k0)     * 64 + n], Wl[(k0 + 1) * 64 + n]);
            v[nt * 2 + 1] = pkh2(Wl[(k0 + 8) * 64 + n], Wl[(k0 + 9) * 64 + n]);
        }
        uint4* dp = (uint4*)(Bl2 + s * BSTRIDE);
        dp[0] = make_uint4(v[0],  v[1],  v[2],  v[3]);
        dp[1] = make_uint4(v[4],  v[5],  v[6],  v[7]);
        dp[2] = make_uint4(v[8],  v[9],  v[10], v[11]);
        dp[3] = make_uint4(v[12], v[13], v[14], v[15]);
    }
    if (t < 64) { bcs[t] = bc[t]; bls[t] = bl[t]; }

    // ---- stage Af: U = [xh | y1h | zh] rows [rowbase, rowbase+128) ----
    for (int idx = t; idx < NKT1 * 8 * 32; idx += 512) {
        const int kt  = idx >> 8;
        const int rem = idx & 255;
        const int rt  = rem >> 5;
        const int ln  = rem & 31;
        const int gg = ln >> 2, tt = ln & 3;
        const int r0 = rt * 16 + gg;
        const __half* p = (kt < 4) ? g_xh : (kt < 8) ? g_y1h : g_zh;
        const int c0 = (kt & 3) * 16 + 2 * tt;
        unsigned a0 = 0, a1 = 0, a2 = 0, a3 = 0;
        const __half* pr = p + (size_t)rowbase * CC;
        if (r0 < nrows) {
            a0 = *(const unsigned*)(pr + (size_t)r0 * CC + c0);
            a2 = *(const unsigned*)(pr + (size_t)r0 * CC + c0 + 8);
        }
        if (r0 + 8 < nrows) {
            a1 = *(const unsigned*)(pr + (size_t)(r0 + 8) * CC + c0);
            a3 = *(const unsigned*)(pr + (size_t)(r0 + 8) * CC + c0 + 8);
        }
        *(uint4*)(Af + idx * 4) = make_uint4(a0, a1, a2, a3);
    }
    __syncthreads();

    const int mtile = w >> 1;     // 0..7 -> rows 16*mtile
    const int nt2   = w & 1;      // 0..1 -> cols 32*nt2
    const int g = lane >> 2, tid = lane & 3;

    // ---- phase 1: h = U @ Wc_folded ----
    float c1[4][4];
#pragma unroll
    for (int n = 0; n < 4; n++)
#pragma unroll
        for (int q = 0; q < 4; q++) c1[n][q] = 0.f;

#pragma unroll
    for (int kt = 0; kt < NKT1; kt++) {
        const uint4 A = *(const uint4*)(Af + ((kt * 8 + mtile) * 32 + lane) * 4);
        const float* bp = Bf + (kt * 32 + lane) * BSTRIDE + nt2 * 8;
        const uint4 B0 = *(const uint4*)(bp);
        const uint4 B1 = *(const uint4*)(bp + 4);
        mma16(c1[0], A.x, A.y, A.z, A.w, B0.x, B0.y);
        mma16(c1[1], A.x, A.y, A.z, A.w, B0.z, B0.w);
        mma16(c1[2], A.x, A.y, A.z, A.w, B1.x, B1.y);
        mma16(c1[3], A.x, A.y, A.z, A.w, B1.z, B1.w);
    }
    __syncthreads();   // all Af reads complete before Hs overlay

    // ---- epilogue 1: bias + relu -> fp16 A-fragments into Hs ----
#pragma unroll
    for (int j = 0; j < 2; j++) {
        const int kt2 = 2 * nt2 + j;
        float v[4][2];
#pragma unroll
        for (int h = 0; h < 2; h++) {
            const int n = 2 * j + h;
            const int Cl = nt2 * 32 + n * 8 + 2 * tid;
            const float b0 = bcs[Cl], b1 = bcs[Cl + 1];
            v[2 * h][0]     = fmaxf(c1[n][0] + b0, 0.f);
            v[2 * h][1]     = fmaxf(c1[n][1] + b1, 0.f);
            v[2 * h + 1][0] = fmaxf(c1[n][2] + b0, 0.f);
            v[2 * h + 1][1] = fmaxf(c1[n][3] + b1, 0.f);
        }
        *(uint4*)(Hs + ((kt2 * 8 + mtile) * 32 + lane) * 4) =
            make_uint4(pkh2(v[0][0], v[0][1]), pkh2(v[1][0], v[1][1]),
                       pkh2(v[2][0], v[2][1]), pkh2(v[3][0], v[3][1]));
    }
    __syncthreads();

    // ---- phase 2: out = h @ Wl ----
    float c2[4][4];
#pragma unroll
    for (int n = 0; n < 4; n++)
#pragma unroll
        for (int q = 0; q < 4; q++) c2[n][q] = 0.f;

#pragma unroll
    for (int kt = 0; kt < NKT2; kt++) {
        const uint4 A = *(const uint4*)(Hs + ((kt * 8 + mtile) * 32 + lane) * 4);
        const float* bp = Bl2 + (kt * 32 + lane) * BSTRIDE + nt2 * 8;
        const uint4 B0 = *(const uint4*)(bp);
        const uint4 B1 = *(const uint4*)(bp + 4);
        mma16(c2[0], A.x, A.y, A.z, A.w, B0.x, B0.y);
        mma16(c2[1], A.x, A.y, A.z, A.w, B0.z, B0.w);
        mma16(c2[2], A.x, A.y, A.z, A.w, B1.x, B1.y);
        mma16(c2[3], A.x, A.y, A.z, A.w, B1.z, B1.w);
    }

    // ---- epilogue 2: bias + store ----
#pragma unroll
    for (int n = 0; n < 4; n++) {
        const int Cl = nt2 * 32 + n * 8 + 2 * tid;
        const float b0 = bls[Cl], b1 = bls[Cl + 1];
        const int Rl = mtile * 16 + g;
        if (Rl < nrows)
            *(float2*)(out + (size_t)(rowbase + Rl) * CC + Cl) =
                make_float2(c2[n][0] + b0, c2[n][1] + b1);
        if (Rl + 8 < nrows)
            *(float2*)(out + (size_t)(rowbase + Rl + 8) * CC + Cl) =
                make_float2(c2[n][2] + b0, c2[n][3] + b1);
    }
}

// ---------------- launch ----------------
extern "C" void kernel_launch(void* const* d_in, const int* in_sizes, int n_in,
                              void* d_out, int out_size) {
    const float* x   = (const float*)d_in[0];
    const int*   src = (const int*)d_in[1];
    const int*   dst = (const int*)d_in[2];
    const float* Wc  = (const float*)d_in[3];
    const float* bc  = (const float*)d_in[4];
    const float* Wl  = (const float*)d_in[5];
    const float* bl  = (const float*)d_in[6];
    float* out = (float*)d_out;

    const int fused_smem = (NKT1 * 8 * 32 * 4 + NKT1 * 32 * BSTRIDE +
                            NKT2 * 32 * BSTRIDE + 128) * 4;   // 90624 B
    static bool attr_set = false;
    if (!attr_set) {
        cudaFuncSetAttribute(k_fused, cudaFuncAttributeMaxDynamicSharedMemorySize,
                             fused_smem);
        attr_set = true;
    }

    __half *xt, *y1h, *y1t, *zh;
    cudaGetSymbolAddress((void**)&xt,  g_xt);
    cudaGetSymbolAddress((void**)&y1h, g_y1h);
    cudaGetSymbolAddress((void**)&y1t, g_y1t);
    cudaGetSymbolAddress((void**)&zh,  g_zh);

    // 1: degrees + edge ranks (g_deg zeroed at load / re-zeroed by k_fill3)
    k_degree<<<(EE + 255) / 256, 256>>>(dst);
    // 2: rowptr + norm
    k_emit2<<<SNB, SBS>>>();
    // 3: atomic-free edge fill + x -> (xh, xt) + re-zero deg
    k_fill3<<<(NROWS * CC / 8 + 255) / 256, 256>>>(src, dst, x);
    // 4: y1 = -norm[d] * sum(x~[src]) ; also y1t = norm*y1 for the next gather
    k_spmm_h<<<(NN + 7) / 8, 256>>>(xt, y1h, y1t, -1.f);
    // 5: z = norm[d] * sum(y1t[src]) = A y1   (y2 folded into GEMM weights)
    k_spmm_h<<<(NN + 7) / 8, 256>>>(y1t, zh, nullptr, 1.f);
    // 6: fused dense (fp16 tensor cores, folded weights, all-fp16 A staging)
    const int nblk = (NROWS + TR - 1) / TR;
    k_fused<<<nblk, 512, fused_smem>>>(Wc, bc, Wl, bl, out);
}